// round 5
// baseline (speedup 1.0000x reference)
#include <cuda_runtime.h>
#include <cstdint>

#define N_NODES    100000
#define N_EDGES    3200000
#define F_IN       128
#define HID        64
#define NUM_GRAPHS 512
#define NUM_CLASSES 2

#define SCAN_BS    256
#define SCAN_NB    ((N_NODES + SCAN_BS - 1) / SCAN_BS)   // 391

// ---------------- scratch (static device globals; no allocation) ----------------
__device__ int    g_cnti[N_NODES];             // in-degree (excl self loop)
__device__ int    g_fill[N_NODES];             // fill cursor for CSR build
__device__ int    g_offs[N_NODES + 1];         // CSR row offsets (by destination)
__device__ int    g_part[SCAN_NB];             // scan partials
__device__ int    g_partex[SCAN_NB];           // scanned partials
__device__ int    g_csr[N_EDGES];              // CSR: source node per edge slot
__device__ float  g_dinv[N_NODES];             // deg^{-1/2} (deg includes self loop)
__device__ float4 g_hs4[N_NODES * 16];         // dinv * (X @ W), 16 float4 per node
__device__ float4 g_h4 [N_NODES * 16];         // layer output

__device__ __forceinline__ float4 f4add(float4 a, float4 b) {
    return make_float4(a.x + b.x, a.y + b.y, a.z + b.z, a.w + b.w);
}

// ---------------- init ----------------
__global__ void init_kernel() {
    int i = blockIdx.x * blockDim.x + threadIdx.x;
    if (i < N_NODES) { g_cnti[i] = 0; g_fill[i] = 0; }
}

// ---------------- degree count (edge_index is int32!) ----------------
__global__ void edge_kernel(const int* __restrict__ ei) {
    int e = blockIdx.x * blockDim.x + threadIdx.x;
    if (e >= N_EDGES) return;
    int c = ei[N_EDGES + e];                    // destination column
    atomicAdd(&g_cnti[c], 1);
}

// ---------------- 3-kernel exclusive scan of g_cnti -> g_offs ----------------
__global__ void scan1_kernel() {
    __shared__ int s[SCAN_BS];
    int i = blockIdx.x * SCAN_BS + threadIdx.x;
    int v = (i < N_NODES) ? g_cnti[i] : 0;
    s[threadIdx.x] = v;
    __syncthreads();
    #pragma unroll
    for (int d = 1; d < SCAN_BS; d <<= 1) {
        int t = (threadIdx.x >= d) ? s[threadIdx.x - d] : 0;
        __syncthreads();
        s[threadIdx.x] += t;
        __syncthreads();
    }
    if (i < N_NODES) g_offs[i] = s[threadIdx.x] - v;   // exclusive within block
    if (threadIdx.x == SCAN_BS - 1) g_part[blockIdx.x] = s[SCAN_BS - 1];
}

__global__ void scan2_kernel() {   // one block, 512 threads >= SCAN_NB
    __shared__ int s[512];
    int v = (threadIdx.x < SCAN_NB) ? g_part[threadIdx.x] : 0;
    s[threadIdx.x] = v;
    __syncthreads();
    #pragma unroll
    for (int d = 1; d < 512; d <<= 1) {
        int t = (threadIdx.x >= d) ? s[threadIdx.x - d] : 0;
        __syncthreads();
        s[threadIdx.x] += t;
        __syncthreads();
    }
    if (threadIdx.x < SCAN_NB) g_partex[threadIdx.x] = s[threadIdx.x] - v;
}

__global__ void scan3_kernel() {
    int i = blockIdx.x * SCAN_BS + threadIdx.x;
    if (i < N_NODES) g_offs[i] += g_partex[blockIdx.x];
    if (i == 0) g_offs[N_NODES] = N_EDGES;
}

// ---------------- CSR fill (scalar int atomic) + dinv ----------------
__global__ void fill_kernel(const int* __restrict__ ei) {
    int e = blockIdx.x * blockDim.x + threadIdx.x;
    if (e >= N_EDGES) return;
    int r = ei[e];
    int c = ei[N_EDGES + e];
    int pos = g_offs[c] + atomicAdd(&g_fill[c], 1);
    g_csr[pos] = r;
}

__global__ void dinv_kernel() {
    int i = blockIdx.x * blockDim.x + threadIdx.x;
    if (i >= N_NODES) return;
    g_dinv[i] = rsqrtf((float)(1 + g_cnti[i]));   // + self loop
}

// ---------------- GEMM: hs = dinv * (X @ W) ----------------
// 256 threads, tile of 16 nodes; thread computes 4 cols (j4, j4+16, j4+32, j4+48).
template<int K, bool FROM_GH>
__global__ __launch_bounds__(256) void gemm_kernel(const float* __restrict__ Xin,
                                                   const float* __restrict__ W,
                                                   int n) {
    constexpr int PAD = 4;
    __shared__ float4 Ws[K * 16];
    __shared__ float  xs[16 * (K + PAD)];

    const float* __restrict__ X = FROM_GH ? (const float*)g_h4 : Xin;

    int tid = threadIdx.x;
    for (int i = tid; i < K * 16; i += 256) {
        int k = i >> 4, j = i & 15;
        Ws[i] = make_float4(W[k * HID + j],
                            W[k * HID + j + 16],
                            W[k * HID + j + 32],
                            W[k * HID + j + 48]);
    }

    int sub = tid >> 4;
    int j4  = tid & 15;

    for (int base = blockIdx.x * 16; base < n; base += gridDim.x * 16) {
        __syncthreads();
        for (int i = tid; i < 16 * K; i += 256) {
            int s = i / K, k = i % K;
            int node = base + s;
            xs[s * (K + PAD) + k] = (node < n) ? X[(size_t)node * K + k] : 0.0f;
        }
        __syncthreads();

        float a0 = 0.f, a1 = 0.f, a2 = 0.f, a3 = 0.f;
        const float* xr = &xs[sub * (K + PAD)];
        #pragma unroll
        for (int k = 0; k < K; k++) {
            float xv = xr[k];
            float4 w = Ws[k * 16 + j4];
            a0 += xv * w.x; a1 += xv * w.y; a2 += xv * w.z; a3 += xv * w.w;
        }

        int node = base + sub;
        if (node < n) {
            float di = g_dinv[node];
            float* hs = (float*)g_hs4;
            size_t o = (size_t)node * HID + j4;
            hs[o]      = a0 * di;
            hs[o + 16] = a1 * di;
            hs[o + 32] = a2 * di;
            hs[o + 48] = a3 * di;
        }
    }
}

// ---------------- aggregate: h = relu(dinv*(hs[self] + sum hs[src]) + b) ----------------
// 16 threads per node; each owns one float4 (4 columns). Atomic-free.
__global__ __launch_bounds__(256) void agg_kernel(const float* __restrict__ b) {
    int t = blockIdx.x * 256 + threadIdx.x;
    int node = t >> 4;
    if (node >= N_NODES) return;
    int lane = t & 15;

    int s = g_offs[node];
    int e = g_offs[node + 1];

    float4 acc = g_hs4[(size_t)node * 16 + lane];   // self loop

    int j = s;
    for (; j + 1 < e; j += 2) {
        int r0 = __ldg(&g_csr[j]);
        int r1 = __ldg(&g_csr[j + 1]);
        float4 v0 = g_hs4[(size_t)r0 * 16 + lane];
        float4 v1 = g_hs4[(size_t)r1 * 16 + lane];
        acc = f4add(acc, v0);
        acc = f4add(acc, v1);
    }
    if (j < e) {
        int r0 = __ldg(&g_csr[j]);
        acc = f4add(acc, g_hs4[(size_t)r0 * 16 + lane]);
    }

    float di = g_dinv[node];
    float4 bb = reinterpret_cast<const float4*>(b)[lane];
    float4 r;
    r.x = fmaxf(di * acc.x + bb.x, 0.f);
    r.y = fmaxf(di * acc.y + bb.y, 0.f);
    r.z = fmaxf(di * acc.z + bb.z, 0.f);
    r.w = fmaxf(di * acc.w + bb.w, 0.f);
    g_h4[(size_t)node * 16 + lane] = r;
}

// ---------------- fused mean-pool + FC (batch is sorted int32 -> segment per graph) ----------------
// One block (256 threads) per graph. Atomic-free.
__global__ __launch_bounds__(256) void pool_fc_kernel(const int* __restrict__ batch,
                                                      const float* __restrict__ Wfc,
                                                      const float* __restrict__ bfc,
                                                      float* __restrict__ out) {
    int g = blockIdx.x;
    __shared__ int s_lo, s_hi;
    if (threadIdx.x == 0) {
        int lo = 0, hi = N_NODES;
        while (lo < hi) { int m = (lo + hi) >> 1; if (batch[m] < g) lo = m + 1; else hi = m; }
        s_lo = lo;
        lo = 0; hi = N_NODES;
        while (lo < hi) { int m = (lo + hi) >> 1; if (batch[m] < g + 1) lo = m + 1; else hi = m; }
        s_hi = lo;
    }
    __syncthreads();
    int start = s_lo, end = s_hi;

    int j = threadIdx.x & 63;     // column
    int r = threadIdx.x >> 6;     // row group 0..3
    const float* h = (const float*)g_h4;

    float acc = 0.f;
    for (int n = start + r; n < end; n += 4)
        acc += h[(size_t)n * HID + j];

    __shared__ float sm[4][64];
    sm[r][j] = acc;
    __syncthreads();

    if (r == 0) {
        float v = sm[0][j] + sm[1][j] + sm[2][j] + sm[3][j];
        float cnt = (float)((end - start) > 0 ? (end - start) : 1);
        float p = v / cnt;
        float w0 = Wfc[j * 2 + 0];
        float w1 = Wfc[j * 2 + 1];
        __syncwarp();
        sm[0][j] = p * w0;
        sm[1][j] = p * w1;
    }
    __syncthreads();

    if (threadIdx.x < 2) {
        float s = 0.f;
        #pragma unroll
        for (int jj = 0; jj < 64; jj++) s += sm[threadIdx.x][jj];
        out[g * 2 + threadIdx.x] = s + bfc[threadIdx.x];
    }
}

// ---------------- launch ----------------
extern "C" void kernel_launch(void* const* d_in, const int* in_sizes, int n_in,
                              void* d_out, int out_size) {
    const float* x     = (const float*)d_in[0];
    const int*   ei    = (const int*)d_in[1];     // int32! (JAX x64 disabled)
    const int*   batch = (const int*)d_in[2];     // int32!
    const float* W1    = (const float*)d_in[3];
    const float* b1    = (const float*)d_in[4];
    const float* W2    = (const float*)d_in[5];
    const float* b2    = (const float*)d_in[6];
    const float* Wfc   = (const float*)d_in[7];
    const float* bfc   = (const float*)d_in[8];
    float* out = (float*)d_out;

    // CSR build (shared by both layers)
    init_kernel <<<(N_NODES + 255) / 256, 256>>>();
    edge_kernel <<<(N_EDGES + 255) / 256, 256>>>(ei);
    scan1_kernel<<<SCAN_NB, SCAN_BS>>>();
    scan2_kernel<<<1, 512>>>();
    scan3_kernel<<<SCAN_NB, SCAN_BS>>>();
    fill_kernel <<<(N_EDGES + 255) / 256, 256>>>(ei);
    dinv_kernel <<<(N_NODES + 255) / 256, 256>>>();

    // layer 1
    gemm_kernel<128, false><<<2048, 256>>>(x, W1, N_NODES);
    agg_kernel<<<(N_NODES * 16 + 255) / 256, 256>>>(b1);

    // layer 2
    gemm_kernel<64, true><<<2048, 256>>>(nullptr, W2, N_NODES);
    agg_kernel<<<(N_NODES * 16 + 255) / 256, 256>>>(b2);

    // fused mean-pool + FC
    pool_fc_kernel<<<NUM_GRAPHS, 256>>>(batch, Wfc, bfc, out);
}

// round 6
// speedup vs baseline: 1.0499x; 1.0499x over previous
#include <cuda_runtime.h>
#include <cstdint>

#define N_NODES    100000
#define N_EDGES    3200000
#define F_IN       128
#define HID        64
#define NUM_GRAPHS 512
#define N_TILES16  (N_NODES / 16)                        // 6250 exact

#define SCAN_BS    256
#define SCAN_NB    ((N_NODES + SCAN_BS - 1) / SCAN_BS)   // 391

// ---------------- scratch (static device globals; no allocation) ----------------
__device__ int    g_cnti[N_NODES];
__device__ int    g_fill[N_NODES];
__device__ int    g_offs[N_NODES + 1];
__device__ int    g_part[SCAN_NB];
__device__ int    g_partex[SCAN_NB];
__device__ int    g_csr[N_EDGES];
__device__ float  g_dinv[N_NODES];
__device__ float4 g_hs4[N_NODES * 16];   // layer-1: dinv * (x @ W1)
__device__ float4 g_hs2[N_NODES * 16];   // layer-2: dinv * (h1 @ W2)
__device__ float4 g_h4 [N_NODES * 16];   // layer-2 output (for pooling)

__device__ __forceinline__ float4 f4add(float4 a, float4 b) {
    return make_float4(a.x + b.x, a.y + b.y, a.z + b.z, a.w + b.w);
}

// ---------------- init ----------------
__global__ void init_kernel() {
    int i = blockIdx.x * blockDim.x + threadIdx.x;
    if (i < N_NODES) { g_cnti[i] = 0; g_fill[i] = 0; }
}

// ---------------- degree count (int4-vectorized) ----------------
__global__ void edge_kernel(const int* __restrict__ ei) {
    int e4 = blockIdx.x * blockDim.x + threadIdx.x;
    if (e4 >= N_EDGES / 4) return;
    int4 c = reinterpret_cast<const int4*>(ei + N_EDGES)[e4];
    atomicAdd(&g_cnti[c.x], 1);
    atomicAdd(&g_cnti[c.y], 1);
    atomicAdd(&g_cnti[c.z], 1);
    atomicAdd(&g_cnti[c.w], 1);
}

// ---------------- 3-kernel exclusive scan of g_cnti -> g_offs ----------------
__global__ void scan1_kernel() {
    __shared__ int s[SCAN_BS];
    int i = blockIdx.x * SCAN_BS + threadIdx.x;
    int v = (i < N_NODES) ? g_cnti[i] : 0;
    s[threadIdx.x] = v;
    __syncthreads();
    #pragma unroll
    for (int d = 1; d < SCAN_BS; d <<= 1) {
        int t = (threadIdx.x >= d) ? s[threadIdx.x - d] : 0;
        __syncthreads();
        s[threadIdx.x] += t;
        __syncthreads();
    }
    if (i < N_NODES) g_offs[i] = s[threadIdx.x] - v;
    if (threadIdx.x == SCAN_BS - 1) g_part[blockIdx.x] = s[SCAN_BS - 1];
}

__global__ void scan2_kernel() {   // one block, 512 threads >= SCAN_NB
    __shared__ int s[512];
    int v = (threadIdx.x < SCAN_NB) ? g_part[threadIdx.x] : 0;
    s[threadIdx.x] = v;
    __syncthreads();
    #pragma unroll
    for (int d = 1; d < 512; d <<= 1) {
        int t = (threadIdx.x >= d) ? s[threadIdx.x - d] : 0;
        __syncthreads();
        s[threadIdx.x] += t;
        __syncthreads();
    }
    if (threadIdx.x < SCAN_NB) g_partex[threadIdx.x] = s[threadIdx.x] - v;
}

__global__ void scan3_kernel() {   // + dinv fused
    int i = blockIdx.x * SCAN_BS + threadIdx.x;
    if (i < N_NODES) {
        g_offs[i] += g_partex[blockIdx.x];
        g_dinv[i] = rsqrtf((float)(1 + g_cnti[i]));   // + self loop
    }
    if (i == 0) g_offs[N_NODES] = N_EDGES;
}

// ---------------- CSR fill (int4-vectorized) ----------------
__global__ void fill_kernel(const int* __restrict__ ei) {
    int e4 = blockIdx.x * blockDim.x + threadIdx.x;
    if (e4 >= N_EDGES / 4) return;
    int4 r = reinterpret_cast<const int4*>(ei)[e4];
    int4 c = reinterpret_cast<const int4*>(ei + N_EDGES)[e4];
    int p;
    p = g_offs[c.x] + atomicAdd(&g_fill[c.x], 1); g_csr[p] = r.x;
    p = g_offs[c.y] + atomicAdd(&g_fill[c.y], 1); g_csr[p] = r.y;
    p = g_offs[c.z] + atomicAdd(&g_fill[c.z], 1); g_csr[p] = r.z;
    p = g_offs[c.w] + atomicAdd(&g_fill[c.w], 1); g_csr[p] = r.w;
}

// ---------------- GEMM1: hs1 = dinv * (X @ W1), 64 accumulators / thread ----------------
// thread = node; K chunked by 32 through smem; W rows broadcast as float4 groups.
#define G1_T 128
__global__ __launch_bounds__(G1_T) void gemm1_kernel(const float* __restrict__ X,
                                                     const float* __restrict__ W) {
    __shared__ float4 Wc[32 * 16];      // W chunk: cols {j, j+16, j+32, j+48}
    __shared__ float  xs[G1_T * 33];    // stride 33 -> conflict-free

    int tid  = threadIdx.x;
    int base = blockIdx.x * G1_T;
    int node = base + tid;

    float a0[16], a1[16], a2[16], a3[16];
    #pragma unroll
    for (int j = 0; j < 16; j++) { a0[j] = a1[j] = a2[j] = a3[j] = 0.f; }

    for (int kc = 0; kc < F_IN; kc += 32) {
        __syncthreads();
        for (int i = tid; i < 32 * 16; i += G1_T) {
            int k = i >> 4, j = i & 15;
            const float* wr = &W[(kc + k) * HID];
            Wc[i] = make_float4(wr[j], wr[j + 16], wr[j + 32], wr[j + 48]);
        }
        for (int i = tid; i < G1_T * 8; i += G1_T) {
            int r = i >> 3, q = i & 7;
            int nd = base + r;
            float4 v = make_float4(0.f, 0.f, 0.f, 0.f);
            if (nd < N_NODES)
                v = *reinterpret_cast<const float4*>(&X[(size_t)nd * F_IN + kc + q * 4]);
            float* p = &xs[r * 33 + q * 4];   // banks (r + 4q) distinct across warp
            p[0] = v.x; p[1] = v.y; p[2] = v.z; p[3] = v.w;
        }
        __syncthreads();

        const float* xr = &xs[tid * 33];
        #pragma unroll 4
        for (int k = 0; k < 32; k++) {
            float xv = xr[k];
            #pragma unroll
            for (int j = 0; j < 16; j++) {
                float4 w = Wc[k * 16 + j];
                a0[j] += xv * w.x; a1[j] += xv * w.y;
                a2[j] += xv * w.z; a3[j] += xv * w.w;
            }
        }
    }

    if (node < N_NODES) {
        float di = g_dinv[node];
        float4* o = &g_hs4[(size_t)node * 16];
        #pragma unroll
        for (int t = 0; t < 4; t++) {
            o[t]      = make_float4(a0[4*t]*di, a0[4*t+1]*di, a0[4*t+2]*di, a0[4*t+3]*di);
            o[t + 4]  = make_float4(a1[4*t]*di, a1[4*t+1]*di, a1[4*t+2]*di, a1[4*t+3]*di);
            o[t + 8]  = make_float4(a2[4*t]*di, a2[4*t+1]*di, a2[4*t+2]*di, a2[4*t+3]*di);
            o[t + 12] = make_float4(a3[4*t]*di, a3[4*t+1]*di, a3[4*t+2]*di, a3[4*t+3]*di);
        }
    }
}

// ---------------- fused: agg layer1 (gather+ReLU+b1) -> in-block GEMM @W2 -> hs2 ----------------
// 256 threads = 16 nodes x 16 lanes; persistent blocks, W2 resident in smem.
__global__ __launch_bounds__(256) void agg1_gemm2_kernel(const float* __restrict__ b1,
                                                         const float* __restrict__ W2) {
    __shared__ float4 W2s[HID * 16];    // 16 KB
    __shared__ float4 hsm4[16 * 17];    // 16 nodes x 68 floats (stride 17 float4)

    int tid = threadIdx.x;
    for (int i = tid; i < HID * 16; i += 256) {
        int k = i >> 4, j = i & 15;
        const float* wr = &W2[k * HID];
        W2s[i] = make_float4(wr[j], wr[j + 16], wr[j + 32], wr[j + 48]);
    }

    int sub  = tid >> 4;    // node within tile
    int lane = tid & 15;    // float4 column group / output col group
    float4 bb = reinterpret_cast<const float4*>(b1)[lane];

    for (int tile = blockIdx.x; tile < N_TILES16; tile += gridDim.x) {
        int node = tile * 16 + sub;
        int s = g_offs[node];
        int e = g_offs[node + 1];

        float4 acc = g_hs4[(size_t)node * 16 + lane];   // self loop
        int j = s;
        for (; j + 3 < e; j += 4) {
            int r0 = g_csr[j], r1 = g_csr[j + 1], r2 = g_csr[j + 2], r3 = g_csr[j + 3];
            float4 v0 = g_hs4[(size_t)r0 * 16 + lane];
            float4 v1 = g_hs4[(size_t)r1 * 16 + lane];
            float4 v2 = g_hs4[(size_t)r2 * 16 + lane];
            float4 v3 = g_hs4[(size_t)r3 * 16 + lane];
            acc = f4add(f4add(f4add(f4add(acc, v0), v1), v2), v3);
        }
        for (; j < e; j++)
            acc = f4add(acc, g_hs4[(size_t)g_csr[j] * 16 + lane]);

        float di = g_dinv[node];
        float4 r;
        r.x = fmaxf(di * acc.x + bb.x, 0.f);
        r.y = fmaxf(di * acc.y + bb.y, 0.f);
        r.z = fmaxf(di * acc.z + bb.z, 0.f);
        r.w = fmaxf(di * acc.w + bb.w, 0.f);

        __syncthreads();                 // prior tile's phase-B reads done
        hsm4[sub * 17 + lane] = r;       // h1 row tile (cols 4*lane..4*lane+3)
        __syncthreads();

        // phase B: hs2[node] = dinv * (h1[node] @ W2); sub = node, lane = col group
        float c0 = 0.f, c1 = 0.f, c2 = 0.f, c3 = 0.f;
        const float* hr = reinterpret_cast<const float*>(hsm4) + sub * 68;
        #pragma unroll 8
        for (int k = 0; k < HID; k++) {
            float xv = hr[k];
            float4 w = W2s[k * 16 + lane];
            c0 += xv * w.x; c1 += xv * w.y; c2 += xv * w.z; c3 += xv * w.w;
        }
        float* o = reinterpret_cast<float*>(&g_hs2[(size_t)node * 16]);
        o[lane]      = c0 * di;
        o[lane + 16] = c1 * di;
        o[lane + 32] = c2 * di;
        o[lane + 48] = c3 * di;
    }
}

// ---------------- agg layer2: h2 = relu(dinv*(hs2_self + sum hs2_src) + b2) ----------------
__global__ __launch_bounds__(256) void agg2_kernel(const float* __restrict__ b) {
    int t = blockIdx.x * 256 + threadIdx.x;
    int node = t >> 4;
    if (node >= N_NODES) return;
    int lane = t & 15;

    int s = g_offs[node];
    int e = g_offs[node + 1];

    float4 acc = g_hs2[(size_t)node * 16 + lane];
    int j = s;
    for (; j + 3 < e; j += 4) {
        int r0 = g_csr[j], r1 = g_csr[j + 1], r2 = g_csr[j + 2], r3 = g_csr[j + 3];
        float4 v0 = g_hs2[(size_t)r0 * 16 + lane];
        float4 v1 = g_hs2[(size_t)r1 * 16 + lane];
        float4 v2 = g_hs2[(size_t)r2 * 16 + lane];
        float4 v3 = g_hs2[(size_t)r3 * 16 + lane];
        acc = f4add(f4add(f4add(f4add(acc, v0), v1), v2), v3);
    }
    for (; j < e; j++)
        acc = f4add(acc, g_hs2[(size_t)g_csr[j] * 16 + lane]);

    float di = g_dinv[node];
    float4 bb = reinterpret_cast<const float4*>(b)[lane];
    float4 r;
    r.x = fmaxf(di * acc.x + bb.x, 0.f);
    r.y = fmaxf(di * acc.y + bb.y, 0.f);
    r.z = fmaxf(di * acc.z + bb.z, 0.f);
    r.w = fmaxf(di * acc.w + bb.w, 0.f);
    g_h4[(size_t)node * 16 + lane] = r;
}

// ---------------- fused mean-pool + FC (batch sorted int32) ----------------
__global__ __launch_bounds__(256) void pool_fc_kernel(const int* __restrict__ batch,
                                                      const float* __restrict__ Wfc,
                                                      const float* __restrict__ bfc,
                                                      float* __restrict__ out) {
    int g = blockIdx.x;
    __shared__ int s_lo, s_hi;
    if (threadIdx.x == 0) {
        int lo = 0, hi = N_NODES;
        while (lo < hi) { int m = (lo + hi) >> 1; if (batch[m] < g) lo = m + 1; else hi = m; }
        s_lo = lo;
        lo = 0; hi = N_NODES;
        while (lo < hi) { int m = (lo + hi) >> 1; if (batch[m] < g + 1) lo = m + 1; else hi = m; }
        s_hi = lo;
    }
    __syncthreads();
    int start = s_lo, end = s_hi;

    int j = threadIdx.x & 63;
    int r = threadIdx.x >> 6;
    const float* h = (const float*)g_h4;

    float acc = 0.f;
    for (int n = start + r; n < end; n += 4)
        acc += h[(size_t)n * HID + j];

    __shared__ float sm[4][64];
    sm[r][j] = acc;
    __syncthreads();

    if (r == 0) {
        float v = sm[0][j] + sm[1][j] + sm[2][j] + sm[3][j];
        float cnt = (float)((end - start) > 0 ? (end - start) : 1);
        float p = v / cnt;
        float w0 = Wfc[j * 2 + 0];
        float w1 = Wfc[j * 2 + 1];
        __syncwarp();
        sm[0][j] = p * w0;
        sm[1][j] = p * w1;
    }
    __syncthreads();

    if (threadIdx.x < 2) {
        float s = 0.f;
        #pragma unroll
        for (int jj = 0; jj < 64; jj++) s += sm[threadIdx.x][jj];
        out[g * 2 + threadIdx.x] = s + bfc[threadIdx.x];
    }
}

// ---------------- launch ----------------
extern "C" void kernel_launch(void* const* d_in, const int* in_sizes, int n_in,
                              void* d_out, int out_size) {
    const float* x     = (const float*)d_in[0];
    const int*   ei    = (const int*)d_in[1];     // int32
    const int*   batch = (const int*)d_in[2];     // int32
    const float* W1    = (const float*)d_in[3];
    const float* b1    = (const float*)d_in[4];
    const float* W2    = (const float*)d_in[5];
    const float* b2    = (const float*)d_in[6];
    const float* Wfc   = (const float*)d_in[7];
    const float* bfc   = (const float*)d_in[8];
    float* out = (float*)d_out;

    // CSR build (shared by both layers)
    init_kernel <<<(N_NODES + 255) / 256, 256>>>();
    edge_kernel <<<(N_EDGES / 4 + 255) / 256, 256>>>(ei);
    scan1_kernel<<<SCAN_NB, SCAN_BS>>>();
    scan2_kernel<<<1, 512>>>();
    scan3_kernel<<<SCAN_NB, SCAN_BS>>>();
    fill_kernel <<<(N_EDGES / 4 + 255) / 256, 256>>>(ei);

    // layer 1 GEMM
    gemm1_kernel<<<(N_NODES + G1_T - 1) / G1_T, G1_T>>>(x, W1);
    // layer 1 aggregation fused with layer 2 GEMM
    agg1_gemm2_kernel<<<2048, 256>>>(b1, W2);
    // layer 2 aggregation
    agg2_kernel<<<(N_NODES * 16 + 255) / 256, 256>>>(b2);

    // fused mean-pool + FC
    pool_fc_kernel<<<NUM_GRAPHS, 256>>>(batch, Wfc, bfc, out);
}

// round 7
// speedup vs baseline: 1.1637x; 1.1084x over previous
#include <cuda_runtime.h>
#include <cuda_fp16.h>
#include <cstdint>

#define N_NODES    100000
#define N_EDGES    3200000
#define F_IN       128
#define HID        64
#define NUM_GRAPHS 512
#define N_TILES16  (N_NODES / 16)                        // 6250 exact

#define SCAN_BS    256
#define SCAN_NB    ((N_NODES + SCAN_BS - 1) / SCAN_BS)   // 391

// ---------------- scratch (static device globals; no allocation) ----------------
__device__ int    g_cnti[N_NODES];
__device__ int    g_fill[N_NODES];
__device__ int    g_offs[N_NODES + 1];
__device__ int    g_part[SCAN_NB];
__device__ int    g_partex[SCAN_NB];
__device__ int    g_csr[N_EDGES];
__device__ float  g_dinv[N_NODES];
__device__ uint2  g_hs1h[N_NODES * 16];   // fp16: dinv * (x @ W1)   (16 uint2 = 64 halves/node)
__device__ uint2  g_hs2h[N_NODES * 16];   // fp16: dinv * (h1 @ W2)
__device__ float4 g_h4 [N_NODES * 16];    // layer-2 output (fp32, for pooling)

__device__ __forceinline__ float4 f4add(float4 a, float4 b) {
    return make_float4(a.x + b.x, a.y + b.y, a.z + b.z, a.w + b.w);
}
__device__ __forceinline__ float4 h4tof4(uint2 u) {
    __half2 a = *reinterpret_cast<__half2*>(&u.x);
    __half2 b = *reinterpret_cast<__half2*>(&u.y);
    float2 fa = __half22float2(a), fb = __half22float2(b);
    return make_float4(fa.x, fa.y, fb.x, fb.y);
}
__device__ __forceinline__ unsigned pack2h(float a, float b) {
    __half2 h = __floats2half2_rn(a, b);
    return *reinterpret_cast<unsigned*>(&h);
}

// ---------------- init ----------------
__global__ void init_kernel() {
    int i = blockIdx.x * blockDim.x + threadIdx.x;
    if (i < N_NODES) g_cnti[i] = 0;
}

// ---------------- degree count (int4-vectorized) ----------------
__global__ void edge_kernel(const int* __restrict__ ei) {
    int e4 = blockIdx.x * blockDim.x + threadIdx.x;
    if (e4 >= N_EDGES / 4) return;
    int4 c = reinterpret_cast<const int4*>(ei + N_EDGES)[e4];
    atomicAdd(&g_cnti[c.x], 1);
    atomicAdd(&g_cnti[c.y], 1);
    atomicAdd(&g_cnti[c.z], 1);
    atomicAdd(&g_cnti[c.w], 1);
}

// ---------------- 3-kernel exclusive scan of g_cnti -> g_offs ----------------
__global__ void scan1_kernel() {
    __shared__ int s[SCAN_BS];
    int i = blockIdx.x * SCAN_BS + threadIdx.x;
    int v = (i < N_NODES) ? g_cnti[i] : 0;
    s[threadIdx.x] = v;
    __syncthreads();
    #pragma unroll
    for (int d = 1; d < SCAN_BS; d <<= 1) {
        int t = (threadIdx.x >= d) ? s[threadIdx.x - d] : 0;
        __syncthreads();
        s[threadIdx.x] += t;
        __syncthreads();
    }
    if (i < N_NODES) g_offs[i] = s[threadIdx.x] - v;
    if (threadIdx.x == SCAN_BS - 1) g_part[blockIdx.x] = s[SCAN_BS - 1];
}

__global__ void scan2_kernel() {   // one block, 512 threads >= SCAN_NB
    __shared__ int s[512];
    int v = (threadIdx.x < SCAN_NB) ? g_part[threadIdx.x] : 0;
    s[threadIdx.x] = v;
    __syncthreads();
    #pragma unroll
    for (int d = 1; d < 512; d <<= 1) {
        int t = (threadIdx.x >= d) ? s[threadIdx.x - d] : 0;
        __syncthreads();
        s[threadIdx.x] += t;
        __syncthreads();
    }
    if (threadIdx.x < SCAN_NB) g_partex[threadIdx.x] = s[threadIdx.x] - v;
}

__global__ void scan3_kernel() {   // + dinv + fill-cursor seed fused
    int i = blockIdx.x * SCAN_BS + threadIdx.x;
    if (i < N_NODES) {
        int o = g_offs[i] + g_partex[blockIdx.x];
        g_offs[i] = o;
        g_fill[i] = o;                                 // cursor starts at row offset
        g_dinv[i] = rsqrtf((float)(1 + g_cnti[i]));    // + self loop
    }
    if (i == 0) g_offs[N_NODES] = N_EDGES;
}

// ---------------- CSR fill (int4-vectorized; cursor IS the position) ----------------
__global__ void fill_kernel(const int* __restrict__ ei) {
    int e4 = blockIdx.x * blockDim.x + threadIdx.x;
    if (e4 >= N_EDGES / 4) return;
    int4 r = reinterpret_cast<const int4*>(ei)[e4];
    int4 c = reinterpret_cast<const int4*>(ei + N_EDGES)[e4];
    g_csr[atomicAdd(&g_fill[c.x], 1)] = r.x;
    g_csr[atomicAdd(&g_fill[c.y], 1)] = r.y;
    g_csr[atomicAdd(&g_fill[c.z], 1)] = r.z;
    g_csr[atomicAdd(&g_fill[c.w], 1)] = r.w;
}

// ---------------- GEMM1: hs1 = fp16( dinv * (X @ W1) ), 64 accumulators / thread ----------------
#define G1_T 128
__global__ __launch_bounds__(G1_T) void gemm1_kernel(const float* __restrict__ X,
                                                     const float* __restrict__ W) {
    __shared__ float4 Wc[32 * 16];      // W chunk: cols {j, j+16, j+32, j+48}
    __shared__ float  xs[G1_T * 33];    // stride 33 -> conflict-free

    int tid  = threadIdx.x;
    int base = blockIdx.x * G1_T;
    int node = base + tid;

    float a0[16], a1[16], a2[16], a3[16];
    #pragma unroll
    for (int j = 0; j < 16; j++) { a0[j] = a1[j] = a2[j] = a3[j] = 0.f; }

    for (int kc = 0; kc < F_IN; kc += 32) {
        __syncthreads();
        for (int i = tid; i < 32 * 16; i += G1_T) {
            int k = i >> 4, j = i & 15;
            const float* wr = &W[(kc + k) * HID];
            Wc[i] = make_float4(wr[j], wr[j + 16], wr[j + 32], wr[j + 48]);
        }
        for (int i = tid; i < G1_T * 8; i += G1_T) {
            int r = i >> 3, q = i & 7;
            int nd = base + r;
            float4 v = make_float4(0.f, 0.f, 0.f, 0.f);
            if (nd < N_NODES)
                v = *reinterpret_cast<const float4*>(&X[(size_t)nd * F_IN + kc + q * 4]);
            float* p = &xs[r * 33 + q * 4];
            p[0] = v.x; p[1] = v.y; p[2] = v.z; p[3] = v.w;
        }
        __syncthreads();

        const float* xr = &xs[tid * 33];
        #pragma unroll 4
        for (int k = 0; k < 32; k++) {
            float xv = xr[k];
            #pragma unroll
            for (int j = 0; j < 16; j++) {
                float4 w = Wc[k * 16 + j];
                a0[j] += xv * w.x; a1[j] += xv * w.y;
                a2[j] += xv * w.z; a3[j] += xv * w.w;
            }
        }
    }

    if (node < N_NODES) {
        float di = g_dinv[node];
        // a0[j]=col j, a1[j]=col 16+j, a2[j]=col 32+j, a3[j]=col 48+j
        uint4* o = reinterpret_cast<uint4*>(&g_hs1h[(size_t)node * 16]);
        float* arr[4] = {a0, a1, a2, a3};
        #pragma unroll
        for (int t = 0; t < 4; t++) {
            float* a = arr[t];
            uint4 u0, u1;
            u0.x = pack2h(a[0]*di,  a[1]*di);  u0.y = pack2h(a[2]*di,  a[3]*di);
            u0.z = pack2h(a[4]*di,  a[5]*di);  u0.w = pack2h(a[6]*di,  a[7]*di);
            u1.x = pack2h(a[8]*di,  a[9]*di);  u1.y = pack2h(a[10]*di, a[11]*di);
            u1.z = pack2h(a[12]*di, a[13]*di); u1.w = pack2h(a[14]*di, a[15]*di);
            o[t * 2]     = u0;
            o[t * 2 + 1] = u1;
        }
    }
}

// ---------------- fused: agg layer1 (fp16 gather+ReLU+b1) -> in-block GEMM @W2 -> hs2 fp16 ----------------
// 256 threads = 16 nodes x 16 lanes; lane owns contiguous cols 4*lane..4*lane+3.
__global__ __launch_bounds__(256) void agg1_gemm2_kernel(const float* __restrict__ b1,
                                                         const float* __restrict__ W2) {
    __shared__ float4 W2s[HID * 16];    // W2s[k*16+j] = W2[k][4j..4j+3]
    __shared__ float4 hsm4[16 * 17];    // 16 nodes x 68 floats

    int tid = threadIdx.x;
    for (int i = tid; i < HID * 16; i += 256) {
        int k = i >> 4, j = i & 15;
        W2s[i] = *reinterpret_cast<const float4*>(&W2[k * HID + j * 4]);
    }

    int sub  = tid >> 4;    // node within tile
    int lane = tid & 15;    // 4-col group
    float4 bb = reinterpret_cast<const float4*>(b1)[lane];

    for (int tile = blockIdx.x; tile < N_TILES16; tile += gridDim.x) {
        int node = tile * 16 + sub;
        int s = g_offs[node];
        int e = g_offs[node + 1];

        float4 acc = h4tof4(g_hs1h[(size_t)node * 16 + lane]);   // self loop
        int j = s;
        for (; j + 3 < e; j += 4) {
            int r0 = g_csr[j], r1 = g_csr[j + 1], r2 = g_csr[j + 2], r3 = g_csr[j + 3];
            float4 v0 = h4tof4(g_hs1h[(size_t)r0 * 16 + lane]);
            float4 v1 = h4tof4(g_hs1h[(size_t)r1 * 16 + lane]);
            float4 v2 = h4tof4(g_hs1h[(size_t)r2 * 16 + lane]);
            float4 v3 = h4tof4(g_hs1h[(size_t)r3 * 16 + lane]);
            acc = f4add(f4add(f4add(f4add(acc, v0), v1), v2), v3);
        }
        for (; j < e; j++)
            acc = f4add(acc, h4tof4(g_hs1h[(size_t)g_csr[j] * 16 + lane]));

        float di = g_dinv[node];
        float4 r;
        r.x = fmaxf(di * acc.x + bb.x, 0.f);
        r.y = fmaxf(di * acc.y + bb.y, 0.f);
        r.z = fmaxf(di * acc.z + bb.z, 0.f);
        r.w = fmaxf(di * acc.w + bb.w, 0.f);

        __syncthreads();                 // prior tile's phase-B reads done
        hsm4[sub * 17 + lane] = r;       // h1 row tile (fp32, cols 4lane..4lane+3)
        __syncthreads();

        // phase B: hs2[node] = fp16( dinv * (h1[node] @ W2) ); cols 4lane..4lane+3
        float c0 = 0.f, c1 = 0.f, c2 = 0.f, c3 = 0.f;
        const float* hr = reinterpret_cast<const float*>(hsm4) + sub * 68;
        #pragma unroll 8
        for (int k = 0; k < HID; k++) {
            float xv = hr[k];
            float4 w = W2s[k * 16 + lane];
            c0 += xv * w.x; c1 += xv * w.y; c2 += xv * w.z; c3 += xv * w.w;
        }
        uint2 u;
        u.x = pack2h(c0 * di, c1 * di);
        u.y = pack2h(c2 * di, c3 * di);
        g_hs2h[(size_t)node * 16 + lane] = u;
    }
}

// ---------------- agg layer2: h2 = relu(dinv*(hs2_self + sum hs2_src) + b2) ----------------
__global__ __launch_bounds__(256) void agg2_kernel(const float* __restrict__ b) {
    int t = blockIdx.x * 256 + threadIdx.x;
    int node = t >> 4;
    if (node >= N_NODES) return;
    int lane = t & 15;

    int s = g_offs[node];
    int e = g_offs[node + 1];

    float4 acc = h4tof4(g_hs2h[(size_t)node * 16 + lane]);
    int j = s;
    for (; j + 3 < e; j += 4) {
        int r0 = g_csr[j], r1 = g_csr[j + 1], r2 = g_csr[j + 2], r3 = g_csr[j + 3];
        float4 v0 = h4tof4(g_hs2h[(size_t)r0 * 16 + lane]);
        float4 v1 = h4tof4(g_hs2h[(size_t)r1 * 16 + lane]);
        float4 v2 = h4tof4(g_hs2h[(size_t)r2 * 16 + lane]);
        float4 v3 = h4tof4(g_hs2h[(size_t)r3 * 16 + lane]);
        acc = f4add(f4add(f4add(f4add(acc, v0), v1), v2), v3);
    }
    for (; j < e; j++)
        acc = f4add(acc, h4tof4(g_hs2h[(size_t)g_csr[j] * 16 + lane]));

    float di = g_dinv[node];
    float4 bb = reinterpret_cast<const float4*>(b)[lane];
    float4 r;
    r.x = fmaxf(di * acc.x + bb.x, 0.f);
    r.y = fmaxf(di * acc.y + bb.y, 0.f);
    r.z = fmaxf(di * acc.z + bb.z, 0.f);
    r.w = fmaxf(di * acc.w + bb.w, 0.f);
    g_h4[(size_t)node * 16 + lane] = r;
}

// ---------------- fused mean-pool + FC (batch sorted int32) ----------------
__global__ __launch_bounds__(256) void pool_fc_kernel(const int* __restrict__ batch,
                                                      const float* __restrict__ Wfc,
                                                      const float* __restrict__ bfc,
                                                      float* __restrict__ out) {
    int g = blockIdx.x;
    __shared__ int s_lo, s_hi;
    if (threadIdx.x == 0) {
        int lo = 0, hi = N_NODES;
        while (lo < hi) { int m = (lo + hi) >> 1; if (batch[m] < g) lo = m + 1; else hi = m; }
        s_lo = lo;
        lo = 0; hi = N_NODES;
        while (lo < hi) { int m = (lo + hi) >> 1; if (batch[m] < g + 1) lo = m + 1; else hi = m; }
        s_hi = lo;
    }
    __syncthreads();
    int start = s_lo, end = s_hi;

    int j = threadIdx.x & 63;
    int r = threadIdx.x >> 6;
    const float* h = (const float*)g_h4;

    float acc = 0.f;
    for (int n = start + r; n < end; n += 4)
        acc += h[(size_t)n * HID + j];

    __shared__ float sm[4][64];
    sm[r][j] = acc;
    __syncthreads();

    if (r == 0) {
        float v = sm[0][j] + sm[1][j] + sm[2][j] + sm[3][j];
        float cnt = (float)((end - start) > 0 ? (end - start) : 1);
        float p = v / cnt;
        float w0 = Wfc[j * 2 + 0];
        float w1 = Wfc[j * 2 + 1];
        __syncwarp();
        sm[0][j] = p * w0;
        sm[1][j] = p * w1;
    }
    __syncthreads();

    if (threadIdx.x < 2) {
        float s = 0.f;
        #pragma unroll
        for (int jj = 0; jj < 64; jj++) s += sm[threadIdx.x][jj];
        out[g * 2 + threadIdx.x] = s + bfc[threadIdx.x];
    }
}

// ---------------- launch ----------------
extern "C" void kernel_launch(void* const* d_in, const int* in_sizes, int n_in,
                              void* d_out, int out_size) {
    const float* x     = (const float*)d_in[0];
    const int*   ei    = (const int*)d_in[1];     // int32
    const int*   batch = (const int*)d_in[2];     // int32
    const float* W1    = (const float*)d_in[3];
    const float* b1    = (const float*)d_in[4];
    const float* W2    = (const float*)d_in[5];
    const float* b2    = (const float*)d_in[6];
    const float* Wfc   = (const float*)d_in[7];
    const float* bfc   = (const float*)d_in[8];
    float* out = (float*)d_out;

    // CSR build (shared by both layers)
    init_kernel <<<(N_NODES + 255) / 256, 256>>>();
    edge_kernel <<<(N_EDGES / 4 + 255) / 256, 256>>>(ei);
    scan1_kernel<<<SCAN_NB, SCAN_BS>>>();
    scan2_kernel<<<1, 512>>>();
    scan3_kernel<<<SCAN_NB, SCAN_BS>>>();
    fill_kernel <<<(N_EDGES / 4 + 255) / 256, 256>>>(ei);

    // layer 1 GEMM (fp16 output)
    gemm1_kernel<<<(N_NODES + G1_T - 1) / G1_T, G1_T>>>(x, W1);
    // layer 1 aggregation fused with layer 2 GEMM (fp16 in/out)
    agg1_gemm2_kernel<<<2048, 256>>>(b1, W2);
    // layer 2 aggregation
    agg2_kernel<<<(N_NODES * 16 + 255) / 256, 256>>>(b2);

    // fused mean-pool + FC
    pool_fc_kernel<<<NUM_GRAPHS, 256>>>(batch, Wfc, bfc, out);
}

// round 9
// speedup vs baseline: 1.2479x; 1.0723x over previous
#include <cuda_runtime.h>
#include <cuda_fp16.h>
#include <cstdint>

#define N_NODES    100000
#define N_EDGES    3200000
#define F_IN       128
#define HID        64
#define NUM_GRAPHS 512
#define N_TILES16  (N_NODES / 16)                        // 6250 exact

#define SCAN_BS    256
#define SCAN_NB    ((N_NODES + SCAN_BS - 1) / SCAN_BS)   // 391

// ---------------- scratch (static device globals; no allocation) ----------------
__device__ int    g_cnti[N_NODES];
__device__ int    g_fill[N_NODES];
__device__ int    g_offs[N_NODES + 1];
__device__ int    g_part[SCAN_NB];
__device__ int    g_partex[SCAN_NB];
__device__ int    g_csr[N_EDGES];
__device__ float  g_dinv[N_NODES];
__device__ uint2  g_hs1h[N_NODES * 16];   // fp16: dinv * (x @ W1)
__device__ uint2  g_hs2h[N_NODES * 16];   // fp16: dinv * (h1 @ W2)
__device__ float4 g_h4 [N_NODES * 16];    // layer-2 output (fp32, for pooling)

__device__ __forceinline__ float4 f4add(float4 a, float4 b) {
    return make_float4(a.x + b.x, a.y + b.y, a.z + b.z, a.w + b.w);
}
__device__ __forceinline__ float4 h4tof4(uint2 u) {
    __half2 a = *reinterpret_cast<__half2*>(&u.x);
    __half2 b = *reinterpret_cast<__half2*>(&u.y);
    float2 fa = __half22float2(a), fb = __half22float2(b);
    return make_float4(fa.x, fa.y, fb.x, fb.y);
}
__device__ __forceinline__ unsigned pack2h(float a, float b) {
    __half2 h = __floats2half2_rn(a, b);
    return *reinterpret_cast<unsigned*>(&h);
}

// ---------------- init ----------------
__global__ void init_kernel() {
    int i = blockIdx.x * blockDim.x + threadIdx.x;
    if (i < N_NODES) g_cnti[i] = 0;
}

// ---------------- degree count (int4-vectorized) ----------------
__global__ void edge_kernel(const int* __restrict__ ei) {
    int e4 = blockIdx.x * blockDim.x + threadIdx.x;
    if (e4 >= N_EDGES / 4) return;
    int4 c = reinterpret_cast<const int4*>(ei + N_EDGES)[e4];
    atomicAdd(&g_cnti[c.x], 1);
    atomicAdd(&g_cnti[c.y], 1);
    atomicAdd(&g_cnti[c.z], 1);
    atomicAdd(&g_cnti[c.w], 1);
}

// ---------------- dinv (only needs degrees; unblocks gemm1 early) ----------------
__global__ void dinv_kernel() {
    int i = blockIdx.x * blockDim.x + threadIdx.x;
    if (i < N_NODES) g_dinv[i] = rsqrtf((float)(1 + g_cnti[i]));   // + self loop
}

// ---------------- 3-kernel exclusive scan of g_cnti -> g_offs ----------------
__global__ void scan1_kernel() {
    __shared__ int s[SCAN_BS];
    int i = blockIdx.x * SCAN_BS + threadIdx.x;
    int v = (i < N_NODES) ? g_cnti[i] : 0;
    s[threadIdx.x] = v;
    __syncthreads();
    #pragma unroll
    for (int d = 1; d < SCAN_BS; d <<= 1) {
        int t = (threadIdx.x >= d) ? s[threadIdx.x - d] : 0;
        __syncthreads();
        s[threadIdx.x] += t;
        __syncthreads();
    }
    if (i < N_NODES) g_offs[i] = s[threadIdx.x] - v;
    if (threadIdx.x == SCAN_BS - 1) g_part[blockIdx.x] = s[SCAN_BS - 1];
}

__global__ void scan2_kernel() {   // one block, 512 threads >= SCAN_NB
    __shared__ int s[512];
    int v = (threadIdx.x < SCAN_NB) ? g_part[threadIdx.x] : 0;
    s[threadIdx.x] = v;
    __syncthreads();
    #pragma unroll
    for (int d = 1; d < 512; d <<= 1) {
        int t = (threadIdx.x >= d) ? s[threadIdx.x - d] : 0;
        __syncthreads();
        s[threadIdx.x] += t;
        __syncthreads();
    }
    if (threadIdx.x < SCAN_NB) g_partex[threadIdx.x] = s[threadIdx.x] - v;
}

__global__ void scan3_kernel() {   // + fill-cursor seed fused
    int i = blockIdx.x * SCAN_BS + threadIdx.x;
    if (i < N_NODES) {
        int o = g_offs[i] + g_partex[blockIdx.x];
        g_offs[i] = o;
        g_fill[i] = o;                                 // cursor starts at row offset
    }
    if (i == 0) g_offs[N_NODES] = N_EDGES;
}

// ---------------- CSR fill (int4-vectorized; cursor IS the position) ----------------
__global__ void fill_kernel(const int* __restrict__ ei) {
    int e4 = blockIdx.x * blockDim.x + threadIdx.x;
    if (e4 >= N_EDGES / 4) return;
    int4 r = reinterpret_cast<const int4*>(ei)[e4];
    int4 c = reinterpret_cast<const int4*>(ei + N_EDGES)[e4];
    g_csr[atomicAdd(&g_fill[c.x], 1)] = r.x;
    g_csr[atomicAdd(&g_fill[c.y], 1)] = r.y;
    g_csr[atomicAdd(&g_fill[c.z], 1)] = r.z;
    g_csr[atomicAdd(&g_fill[c.w], 1)] = r.w;
}

// ---------------- GEMM1: hs1 = fp16( dinv * (X @ W1) ), 64 accumulators / thread ----------------
#define G1_T 128
__global__ __launch_bounds__(G1_T) void gemm1_kernel(const float* __restrict__ X,
                                                     const float* __restrict__ W) {
    __shared__ float4 Wc[32 * 16];      // W chunk: cols {j, j+16, j+32, j+48}
    __shared__ float  xs[G1_T * 33];    // stride 33 -> conflict-free

    int tid  = threadIdx.x;
    int base = blockIdx.x * G1_T;
    int node = base + tid;

    float a0[16], a1[16], a2[16], a3[16];
    #pragma unroll
    for (int j = 0; j < 16; j++) { a0[j] = a1[j] = a2[j] = a3[j] = 0.f; }

    for (int kc = 0; kc < F_IN; kc += 32) {
        __syncthreads();
        for (int i = tid; i < 32 * 16; i += G1_T) {
            int k = i >> 4, j = i & 15;
            const float* wr = &W[(kc + k) * HID];
            Wc[i] = make_float4(wr[j], wr[j + 16], wr[j + 32], wr[j + 48]);
        }
        for (int i = tid; i < G1_T * 8; i += G1_T) {
            int r = i >> 3, q = i & 7;
            int nd = base + r;
            float4 v = make_float4(0.f, 0.f, 0.f, 0.f);
            if (nd < N_NODES)
                v = *reinterpret_cast<const float4*>(&X[(size_t)nd * F_IN + kc + q * 4]);
            float* p = &xs[r * 33 + q * 4];
            p[0] = v.x; p[1] = v.y; p[2] = v.z; p[3] = v.w;
        }
        __syncthreads();

        const float* xr = &xs[tid * 33];
        #pragma unroll 4
        for (int k = 0; k < 32; k++) {
            float xv = xr[k];
            #pragma unroll
            for (int j = 0; j < 16; j++) {
                float4 w = Wc[k * 16 + j];
                a0[j] += xv * w.x; a1[j] += xv * w.y;
                a2[j] += xv * w.z; a3[j] += xv * w.w;
            }
        }
    }

    if (node < N_NODES) {
        float di = g_dinv[node];
        uint4* o = reinterpret_cast<uint4*>(&g_hs1h[(size_t)node * 16]);
        float* arr[4] = {a0, a1, a2, a3};
        #pragma unroll
        for (int t = 0; t < 4; t++) {
            float* a = arr[t];
            uint4 u0, u1;
            u0.x = pack2h(a[0]*di,  a[1]*di);  u0.y = pack2h(a[2]*di,  a[3]*di);
            u0.z = pack2h(a[4]*di,  a[5]*di);  u0.w = pack2h(a[6]*di,  a[7]*di);
            u1.x = pack2h(a[8]*di,  a[9]*di);  u1.y = pack2h(a[10]*di, a[11]*di);
            u1.z = pack2h(a[12]*di, a[13]*di); u1.w = pack2h(a[14]*di, a[15]*di);
            o[t * 2]     = u0;
            o[t * 2 + 1] = u1;
        }
    }
}

// ---------------- fused: agg layer1 (fp16 gather+ReLU+b1) -> in-block GEMM @W2 -> hs2 fp16 ----------------
__global__ __launch_bounds__(256) void agg1_gemm2_kernel(const float* __restrict__ b1,
                                                         const float* __restrict__ W2) {
    __shared__ float4 W2s[HID * 16];    // W2s[k*16+j] = W2[k][4j..4j+3]
    __shared__ float4 hsm4[16 * 17];    // 16 nodes x 68 floats

    int tid = threadIdx.x;
    for (int i = tid; i < HID * 16; i += 256) {
        int k = i >> 4, j = i & 15;
        W2s[i] = *reinterpret_cast<const float4*>(&W2[k * HID + j * 4]);
    }

    int sub  = tid >> 4;    // node within tile
    int lane = tid & 15;    // 4-col group
    float4 bb = reinterpret_cast<const float4*>(b1)[lane];

    for (int tile = blockIdx.x; tile < N_TILES16; tile += gridDim.x) {
        int node = tile * 16 + sub;
        int s = g_offs[node];
        int e = g_offs[node + 1];

        float4 acc = h4tof4(g_hs1h[(size_t)node * 16 + lane]);   // self loop
        int j = s;
        for (; j + 7 < e; j += 8) {
            float4 v0 = h4tof4(g_hs1h[(size_t)g_csr[j    ] * 16 + lane]);
            float4 v1 = h4tof4(g_hs1h[(size_t)g_csr[j + 1] * 16 + lane]);
            float4 v2 = h4tof4(g_hs1h[(size_t)g_csr[j + 2] * 16 + lane]);
            float4 v3 = h4tof4(g_hs1h[(size_t)g_csr[j + 3] * 16 + lane]);
            float4 v4 = h4tof4(g_hs1h[(size_t)g_csr[j + 4] * 16 + lane]);
            float4 v5 = h4tof4(g_hs1h[(size_t)g_csr[j + 5] * 16 + lane]);
            float4 v6 = h4tof4(g_hs1h[(size_t)g_csr[j + 6] * 16 + lane]);
            float4 v7 = h4tof4(g_hs1h[(size_t)g_csr[j + 7] * 16 + lane]);
            acc = f4add(acc, f4add(f4add(f4add(v0, v1), f4add(v2, v3)),
                                   f4add(f4add(v4, v5), f4add(v6, v7))));
        }
        for (; j < e; j++)
            acc = f4add(acc, h4tof4(g_hs1h[(size_t)g_csr[j] * 16 + lane]));

        float di = g_dinv[node];
        float4 r;
        r.x = fmaxf(di * acc.x + bb.x, 0.f);
        r.y = fmaxf(di * acc.y + bb.y, 0.f);
        r.z = fmaxf(di * acc.z + bb.z, 0.f);
        r.w = fmaxf(di * acc.w + bb.w, 0.f);

        __syncthreads();                 // prior tile's phase-B reads done
        hsm4[sub * 17 + lane] = r;
        __syncthreads();

        // phase B: hs2[node] = fp16( dinv * (h1[node] @ W2) )
        float c0 = 0.f, c1 = 0.f, c2 = 0.f, c3 = 0.f;
        const float* hr = reinterpret_cast<const float*>(hsm4) + sub * 68;
        #pragma unroll 8
        for (int k = 0; k < HID; k++) {
            float xv = hr[k];
            float4 w = W2s[k * 16 + lane];
            c0 += xv * w.x; c1 += xv * w.y; c2 += xv * w.z; c3 += xv * w.w;
        }
        uint2 u;
        u.x = pack2h(c0 * di, c1 * di);
        u.y = pack2h(c2 * di, c3 * di);
        g_hs2h[(size_t)node * 16 + lane] = u;
    }
}

// ---------------- agg layer2: h2 = relu(dinv*(hs2_self + sum hs2_src) + b2) ----------------
__global__ __launch_bounds__(256) void agg2_kernel(const float* __restrict__ b) {
    int t = blockIdx.x * 256 + threadIdx.x;
    int node = t >> 4;
    if (node >= N_NODES) return;
    int lane = t & 15;

    int s = g_offs[node];
    int e = g_offs[node + 1];

    float4 acc = h4tof4(g_hs2h[(size_t)node * 16 + lane]);
    int j = s;
    for (; j + 7 < e; j += 8) {
        float4 v0 = h4tof4(g_hs2h[(size_t)g_csr[j    ] * 16 + lane]);
        float4 v1 = h4tof4(g_hs2h[(size_t)g_csr[j + 1] * 16 + lane]);
        float4 v2 = h4tof4(g_hs2h[(size_t)g_csr[j + 2] * 16 + lane]);
        float4 v3 = h4tof4(g_hs2h[(size_t)g_csr[j + 3] * 16 + lane]);
        float4 v4 = h4tof4(g_hs2h[(size_t)g_csr[j + 4] * 16 + lane]);
        float4 v5 = h4tof4(g_hs2h[(size_t)g_csr[j + 5] * 16 + lane]);
        float4 v6 = h4tof4(g_hs2h[(size_t)g_csr[j + 6] * 16 + lane]);
        float4 v7 = h4tof4(g_hs2h[(size_t)g_csr[j + 7] * 16 + lane]);
        acc = f4add(acc, f4add(f4add(f4add(v0, v1), f4add(v2, v3)),
                               f4add(f4add(v4, v5), f4add(v6, v7))));
    }
    for (; j < e; j++)
        acc = f4add(acc, h4tof4(g_hs2h[(size_t)g_csr[j] * 16 + lane]));

    float di = g_dinv[node];
    float4 bb = reinterpret_cast<const float4*>(b)[lane];
    float4 r;
    r.x = fmaxf(di * acc.x + bb.x, 0.f);
    r.y = fmaxf(di * acc.y + bb.y, 0.f);
    r.z = fmaxf(di * acc.z + bb.z, 0.f);
    r.w = fmaxf(di * acc.w + bb.w, 0.f);
    g_h4[(size_t)node * 16 + lane] = r;
}

// ---------------- fused mean-pool + FC (batch sorted int32) ----------------
__global__ __launch_bounds__(256) void pool_fc_kernel(const int* __restrict__ batch,
                                                      const float* __restrict__ Wfc,
                                                      const float* __restrict__ bfc,
                                                      float* __restrict__ out) {
    int g = blockIdx.x;
    __shared__ int s_lo, s_hi;
    if (threadIdx.x == 0) {
        int lo = 0, hi = N_NODES;
        while (lo < hi) { int m = (lo + hi) >> 1; if (batch[m] < g) lo = m + 1; else hi = m; }
        s_lo = lo;
        lo = 0; hi = N_NODES;
        while (lo < hi) { int m = (lo + hi) >> 1; if (batch[m] < g + 1) lo = m + 1; else hi = m; }
        s_hi = lo;
    }
    __syncthreads();
    int start = s_lo, end = s_hi;

    int j = threadIdx.x & 63;
    int r = threadIdx.x >> 6;
    const float* h = (const float*)g_h4;

    float acc = 0.f;
    for (int n = start + r; n < end; n += 4)
        acc += h[(size_t)n * HID + j];

    __shared__ float sm[4][64];
    sm[r][j] = acc;
    __syncthreads();

    if (r == 0) {
        float v = sm[0][j] + sm[1][j] + sm[2][j] + sm[3][j];
        float cnt = (float)((end - start) > 0 ? (end - start) : 1);
        float p = v / cnt;
        float w0 = Wfc[j * 2 + 0];
        float w1 = Wfc[j * 2 + 1];
        __syncwarp();
        sm[0][j] = p * w0;
        sm[1][j] = p * w1;
    }
    __syncthreads();

    if (threadIdx.x < 2) {
        float s = 0.f;
        #pragma unroll
        for (int jj = 0; jj < 64; jj++) s += sm[threadIdx.x][jj];
        out[g * 2 + threadIdx.x] = s + bfc[threadIdx.x];
    }
}

// ---------------- launch (fork/join: gemm1 overlaps scan+fill) ----------------
extern "C" void kernel_launch(void* const* d_in, const int* in_sizes, int n_in,
                              void* d_out, int out_size) {
    const float* x     = (const float*)d_in[0];
    const int*   ei    = (const int*)d_in[1];     // int32
    const int*   batch = (const int*)d_in[2];     // int32
    const float* W1    = (const float*)d_in[3];
    const float* b1    = (const float*)d_in[4];
    const float* W2    = (const float*)d_in[5];
    const float* b2    = (const float*)d_in[6];
    const float* Wfc   = (const float*)d_in[7];
    const float* bfc   = (const float*)d_in[8];
    float* out = (float*)d_out;

    // one-time host-side resources (created on uncaptured correctness call)
    static cudaStream_t s2 = nullptr;
    static cudaEvent_t  evA = nullptr, evB = nullptr;
    if (!s2) {
        cudaStreamCreateWithFlags(&s2, cudaStreamNonBlocking);
        cudaEventCreateWithFlags(&evA, cudaEventDisableTiming);
        cudaEventCreateWithFlags(&evB, cudaEventDisableTiming);
    }

    // degrees -> dinv (prerequisite for both branches)
    init_kernel <<<(N_NODES + 255) / 256, 256>>>();
    edge_kernel <<<(N_EDGES / 4 + 255) / 256, 256>>>(ei);
    dinv_kernel <<<(N_NODES + 255) / 256, 256>>>();

    // fork: gemm1 on s2, CSR build continues on default stream
    cudaEventRecord(evA, 0);
    cudaStreamWaitEvent(s2, evA, 0);
    gemm1_kernel<<<(N_NODES + G1_T - 1) / G1_T, G1_T, 0, s2>>>(x, W1);
    cudaEventRecord(evB, s2);

    scan1_kernel<<<SCAN_NB, SCAN_BS>>>();
    scan2_kernel<<<1, 512>>>();
    scan3_kernel<<<SCAN_NB, SCAN_BS>>>();
    fill_kernel <<<(N_EDGES / 4 + 255) / 256, 256>>>(ei);

    // join
    cudaStreamWaitEvent(0, evB, 0);

    // layer 1 aggregation fused with layer 2 GEMM
    agg1_gemm2_kernel<<<2048, 256>>>(b1, W2);
    // layer 2 aggregation
    agg2_kernel<<<(N_NODES * 16 + 255) / 256, 256>>>(b2);
    // fused mean-pool + FC
    pool_fc_kernel<<<NUM_GRAPHS, 256>>>(batch, Wfc, bfc, out);
}

// round 10
// speedup vs baseline: 1.4469x; 1.1595x over previous
#include <cuda_runtime.h>
#include <cuda_fp16.h>
#include <cstdint>

#define N_NODES    100000
#define N_EDGES    3200000
#define F_IN       128
#define HID        64
#define NUM_GRAPHS 512
#define N_TILES16  (N_NODES / 16)                        // 6250 exact

#define SCAN_BS    256
#define SCAN_NB    ((N_NODES + SCAN_BS - 1) / SCAN_BS)   // 391

// ---------------- scratch (static device globals; no allocation) ----------------
__device__ int    g_cnti[N_NODES];
__device__ int    g_fill[N_NODES];
__device__ int    g_offs[N_NODES + 1];
__device__ int    g_part[SCAN_NB];
__device__ int    g_partex[SCAN_NB];
__device__ int    g_csr[N_EDGES];
__device__ float  g_dinv[N_NODES];
__device__ uint2  g_hs1h[N_NODES * 16];   // fp16: dinv * (x @ W1)
__device__ uint2  g_hs2h[N_NODES * 16];   // fp16: dinv * (h1 @ W2)
__device__ float4 g_h4 [N_NODES * 16];    // layer-2 output (fp32, for pooling)

__device__ __forceinline__ float4 f4add(float4 a, float4 b) {
    return make_float4(a.x + b.x, a.y + b.y, a.z + b.z, a.w + b.w);
}
__device__ __forceinline__ float4 h4tof4(uint2 u) {
    __half2 a = *reinterpret_cast<__half2*>(&u.x);
    __half2 b = *reinterpret_cast<__half2*>(&u.y);
    float2 fa = __half22float2(a), fb = __half22float2(b);
    return make_float4(fa.x, fa.y, fb.x, fb.y);
}
__device__ __forceinline__ unsigned pack2h(float a, float b) {
    __half2 h = __floats2half2_rn(a, b);
    return *reinterpret_cast<unsigned*>(&h);
}
__device__ __forceinline__ float to_tf32(float x) {
    float r;
    asm("cvt.rna.tf32.f32 %0, %1;" : "=f"(r) : "f"(x));
    return r;
}

// ---------------- init ----------------
__global__ void init_kernel() {
    int i = blockIdx.x * blockDim.x + threadIdx.x;
    if (i < N_NODES) g_cnti[i] = 0;
}

// ---------------- degree count (int4-vectorized) ----------------
__global__ void edge_kernel(const int* __restrict__ ei) {
    int e4 = blockIdx.x * blockDim.x + threadIdx.x;
    if (e4 >= N_EDGES / 4) return;
    int4 c = reinterpret_cast<const int4*>(ei + N_EDGES)[e4];
    atomicAdd(&g_cnti[c.x], 1);
    atomicAdd(&g_cnti[c.y], 1);
    atomicAdd(&g_cnti[c.z], 1);
    atomicAdd(&g_cnti[c.w], 1);
}

// ---------------- dinv (only needs degrees; unblocks gemm1 early) ----------------
__global__ void dinv_kernel() {
    int i = blockIdx.x * blockDim.x + threadIdx.x;
    if (i < N_NODES) g_dinv[i] = rsqrtf((float)(1 + g_cnti[i]));   // + self loop
}

// ---------------- 3-kernel exclusive scan of g_cnti -> g_offs ----------------
__global__ void scan1_kernel() {
    __shared__ int s[SCAN_BS];
    int i = blockIdx.x * SCAN_BS + threadIdx.x;
    int v = (i < N_NODES) ? g_cnti[i] : 0;
    s[threadIdx.x] = v;
    __syncthreads();
    #pragma unroll
    for (int d = 1; d < SCAN_BS; d <<= 1) {
        int t = (threadIdx.x >= d) ? s[threadIdx.x - d] : 0;
        __syncthreads();
        s[threadIdx.x] += t;
        __syncthreads();
    }
    if (i < N_NODES) g_offs[i] = s[threadIdx.x] - v;
    if (threadIdx.x == SCAN_BS - 1) g_part[blockIdx.x] = s[SCAN_BS - 1];
}

__global__ void scan2_kernel() {   // one block, 512 threads >= SCAN_NB
    __shared__ int s[512];
    int v = (threadIdx.x < SCAN_NB) ? g_part[threadIdx.x] : 0;
    s[threadIdx.x] = v;
    __syncthreads();
    #pragma unroll
    for (int d = 1; d < 512; d <<= 1) {
        int t = (threadIdx.x >= d) ? s[threadIdx.x - d] : 0;
        __syncthreads();
        s[threadIdx.x] += t;
        __syncthreads();
    }
    if (threadIdx.x < SCAN_NB) g_partex[threadIdx.x] = s[threadIdx.x] - v;
}

__global__ void scan3_kernel() {   // + fill-cursor seed fused
    int i = blockIdx.x * SCAN_BS + threadIdx.x;
    if (i < N_NODES) {
        int o = g_offs[i] + g_partex[blockIdx.x];
        g_offs[i] = o;
        g_fill[i] = o;                                 // cursor starts at row offset
    }
    if (i == 0) g_offs[N_NODES] = N_EDGES;
}

// ---------------- CSR fill (int4-vectorized; cursor IS the position) ----------------
__global__ void fill_kernel(const int* __restrict__ ei) {
    int e4 = blockIdx.x * blockDim.x + threadIdx.x;
    if (e4 >= N_EDGES / 4) return;
    int4 r = reinterpret_cast<const int4*>(ei)[e4];
    int4 c = reinterpret_cast<const int4*>(ei + N_EDGES)[e4];
    g_csr[atomicAdd(&g_fill[c.x], 1)] = r.x;
    g_csr[atomicAdd(&g_fill[c.y], 1)] = r.y;
    g_csr[atomicAdd(&g_fill[c.z], 1)] = r.z;
    g_csr[atomicAdd(&g_fill[c.w], 1)] = r.w;
}

// ---------------- GEMM1 via tf32 tensor cores: hs1 = fp16( dinv * (X @ W1) ) ----------------
// mma.m16n8k8.tf32: warp = 16 nodes x 64 cols. 4 warps/block = 64 nodes/block.
__global__ __launch_bounds__(128) void gemm1_kernel(const float* __restrict__ X,
                                                    const float* __restrict__ W) {
    __shared__ float Wsm[F_IN * 72];    // [k][n], n padded 64->72 (bank-conflict-free B frags)

    int tid = threadIdx.x;
    // load W1 (128x64) -> smem, tf32-rounded
    for (int i2 = tid; i2 < F_IN * HID / 2; i2 += 128) {
        float2 w = reinterpret_cast<const float2*>(W)[i2];
        int k = i2 >> 5, n2 = i2 & 31;
        Wsm[k * 72 + n2 * 2]     = to_tf32(w.x);
        Wsm[k * 72 + n2 * 2 + 1] = to_tf32(w.y);
    }

    int wid  = tid >> 5, lane = tid & 31;
    int gid  = lane >> 2;          // 0..7
    int tig  = lane & 3;           // 0..3
    int node0 = (blockIdx.x * 4 + wid) * 16;
    int r0 = node0 + gid;          // rows handled by this thread
    int r1 = node0 + gid + 8;
    bool v0 = r0 < N_NODES, v1 = r1 < N_NODES;

    // preload all A fragments (16 k-chunks x 4 regs), tf32-rounded
    float a[16][4];
    #pragma unroll
    for (int c = 0; c < 16; c++) {
        int k0 = c * 8 + tig;
        a[c][0] = v0 ? X[(size_t)r0 * F_IN + k0]     : 0.f;
        a[c][1] = v1 ? X[(size_t)r1 * F_IN + k0]     : 0.f;
        a[c][2] = v0 ? X[(size_t)r0 * F_IN + k0 + 4] : 0.f;
        a[c][3] = v1 ? X[(size_t)r1 * F_IN + k0 + 4] : 0.f;
    }
    #pragma unroll
    for (int c = 0; c < 16; c++) {
        a[c][0] = to_tf32(a[c][0]); a[c][1] = to_tf32(a[c][1]);
        a[c][2] = to_tf32(a[c][2]); a[c][3] = to_tf32(a[c][3]);
    }

    float di0 = v0 ? g_dinv[r0] : 0.f;
    float di1 = v1 ? g_dinv[r1] : 0.f;
    __syncthreads();

    unsigned* outp = reinterpret_cast<unsigned*>(g_hs1h);   // 32 uint (=64 half) per node

    #pragma unroll
    for (int nb = 0; nb < 8; nb++) {        // n-tile: cols nb*8 .. nb*8+7
        float c0 = 0.f, c1 = 0.f, c2 = 0.f, c3 = 0.f;
        #pragma unroll
        for (int kc = 0; kc < 16; kc++) {
            float b0 = Wsm[(kc * 8 + tig)     * 72 + nb * 8 + gid];
            float b1 = Wsm[(kc * 8 + tig + 4) * 72 + nb * 8 + gid];
            asm volatile(
                "mma.sync.aligned.m16n8k8.row.col.f32.tf32.tf32.f32 "
                "{%0,%1,%2,%3}, {%4,%5,%6,%7}, {%8,%9}, {%0,%1,%2,%3};"
                : "+f"(c0), "+f"(c1), "+f"(c2), "+f"(c3)
                : "r"(__float_as_uint(a[kc][0])), "r"(__float_as_uint(a[kc][1])),
                  "r"(__float_as_uint(a[kc][2])), "r"(__float_as_uint(a[kc][3])),
                  "r"(__float_as_uint(b0)), "r"(__float_as_uint(b1)));
        }
        // c0,c1 -> row r0 cols (nb*8+2tig, +1); c2,c3 -> row r1 same cols
        if (v0) outp[(size_t)r0 * 32 + nb * 4 + tig] = pack2h(c0 * di0, c1 * di0);
        if (v1) outp[(size_t)r1 * 32 + nb * 4 + tig] = pack2h(c2 * di1, c3 * di1);
    }
}

// ---------------- fused: agg layer1 (fp16 gather+ReLU+b1) -> in-block GEMM @W2 -> hs2 fp16 ----------------
__global__ __launch_bounds__(256) void agg1_gemm2_kernel(const float* __restrict__ b1,
                                                         const float* __restrict__ W2) {
    __shared__ float4 W2s[HID * 16];    // W2s[k*16+j] = W2[k][4j..4j+3]
    __shared__ float4 hsm4[16 * 17];    // 16 nodes x 68 floats

    int tid = threadIdx.x;
    for (int i = tid; i < HID * 16; i += 256) {
        int k = i >> 4, j = i & 15;
        W2s[i] = *reinterpret_cast<const float4*>(&W2[k * HID + j * 4]);
    }

    int sub  = tid >> 4;    // node within tile
    int lane = tid & 15;    // 4-col group
    float4 bb = reinterpret_cast<const float4*>(b1)[lane];

    for (int tile = blockIdx.x; tile < N_TILES16; tile += gridDim.x) {
        int node = tile * 16 + sub;
        int s = g_offs[node];
        int e = g_offs[node + 1];

        float4 acc = h4tof4(g_hs1h[(size_t)node * 16 + lane]);   // self loop
        int j = s;
        for (; j + 7 < e; j += 8) {
            float4 v0 = h4tof4(g_hs1h[(size_t)g_csr[j    ] * 16 + lane]);
            float4 v1 = h4tof4(g_hs1h[(size_t)g_csr[j + 1] * 16 + lane]);
            float4 v2 = h4tof4(g_hs1h[(size_t)g_csr[j + 2] * 16 + lane]);
            float4 v3 = h4tof4(g_hs1h[(size_t)g_csr[j + 3] * 16 + lane]);
            float4 v4 = h4tof4(g_hs1h[(size_t)g_csr[j + 4] * 16 + lane]);
            float4 v5 = h4tof4(g_hs1h[(size_t)g_csr[j + 5] * 16 + lane]);
            float4 v6 = h4tof4(g_hs1h[(size_t)g_csr[j + 6] * 16 + lane]);
            float4 v7 = h4tof4(g_hs1h[(size_t)g_csr[j + 7] * 16 + lane]);
            acc = f4add(acc, f4add(f4add(f4add(v0, v1), f4add(v2, v3)),
                                   f4add(f4add(v4, v5), f4add(v6, v7))));
        }
        for (; j < e; j++)
            acc = f4add(acc, h4tof4(g_hs1h[(size_t)g_csr[j] * 16 + lane]));

        float di = g_dinv[node];
        float4 r;
        r.x = fmaxf(di * acc.x + bb.x, 0.f);
        r.y = fmaxf(di * acc.y + bb.y, 0.f);
        r.z = fmaxf(di * acc.z + bb.z, 0.f);
        r.w = fmaxf(di * acc.w + bb.w, 0.f);

        __syncthreads();                 // prior tile's phase-B reads done
        hsm4[sub * 17 + lane] = r;
        __syncthreads();

        // phase B: hs2[node] = fp16( dinv * (h1[node] @ W2) )
        float c0 = 0.f, c1 = 0.f, c2 = 0.f, c3 = 0.f;
        const float* hr = reinterpret_cast<const float*>(hsm4) + sub * 68;
        #pragma unroll 8
        for (int k = 0; k < HID; k++) {
            float xv = hr[k];
            float4 w = W2s[k * 16 + lane];
            c0 += xv * w.x; c1 += xv * w.y; c2 += xv * w.z; c3 += xv * w.w;
        }
        uint2 u;
        u.x = pack2h(c0 * di, c1 * di);
        u.y = pack2h(c2 * di, c3 * di);
        g_hs2h[(size_t)node * 16 + lane] = u;
    }
}

// ---------------- agg layer2: h2 = relu(dinv*(hs2_self + sum hs2_src) + b2) ----------------
__global__ __launch_bounds__(256) void agg2_kernel(const float* __restrict__ b) {
    int t = blockIdx.x * 256 + threadIdx.x;
    int node = t >> 4;
    if (node >= N_NODES) return;
    int lane = t & 15;

    int s = g_offs[node];
    int e = g_offs[node + 1];

    float4 acc = h4tof4(g_hs2h[(size_t)node * 16 + lane]);
    int j = s;
    for (; j + 7 < e; j += 8) {
        float4 v0 = h4tof4(g_hs2h[(size_t)g_csr[j    ] * 16 + lane]);
        float4 v1 = h4tof4(g_hs2h[(size_t)g_csr[j + 1] * 16 + lane]);
        float4 v2 = h4tof4(g_hs2h[(size_t)g_csr[j + 2] * 16 + lane]);
        float4 v3 = h4tof4(g_hs2h[(size_t)g_csr[j + 3] * 16 + lane]);
        float4 v4 = h4tof4(g_hs2h[(size_t)g_csr[j + 4] * 16 + lane]);
        float4 v5 = h4tof4(g_hs2h[(size_t)g_csr[j + 5] * 16 + lane]);
        float4 v6 = h4tof4(g_hs2h[(size_t)g_csr[j + 6] * 16 + lane]);
        float4 v7 = h4tof4(g_hs2h[(size_t)g_csr[j + 7] * 16 + lane]);
        acc = f4add(acc, f4add(f4add(f4add(v0, v1), f4add(v2, v3)),
                               f4add(f4add(v4, v5), f4add(v6, v7))));
    }
    for (; j < e; j++)
        acc = f4add(acc, h4tof4(g_hs2h[(size_t)g_csr[j] * 16 + lane]));

    float di = g_dinv[node];
    float4 bb = reinterpret_cast<const float4*>(b)[lane];
    float4 r;
    r.x = fmaxf(di * acc.x + bb.x, 0.f);
    r.y = fmaxf(di * acc.y + bb.y, 0.f);
    r.z = fmaxf(di * acc.z + bb.z, 0.f);
    r.w = fmaxf(di * acc.w + bb.w, 0.f);
    g_h4[(size_t)node * 16 + lane] = r;
}

// ---------------- fused mean-pool + FC (batch sorted int32) ----------------
__global__ __launch_bounds__(256) void pool_fc_kernel(const int* __restrict__ batch,
                                                      const float* __restrict__ Wfc,
                                                      const float* __restrict__ bfc,
                                                      float* __restrict__ out) {
    int g = blockIdx.x;
    __shared__ int s_lo, s_hi;
    if (threadIdx.x == 0) {
        int lo = 0, hi = N_NODES;
        while (lo < hi) { int m = (lo + hi) >> 1; if (batch[m] < g) lo = m + 1; else hi = m; }
        s_lo = lo;
        lo = 0; hi = N_NODES;
        while (lo < hi) { int m = (lo + hi) >> 1; if (batch[m] < g + 1) lo = m + 1; else hi = m; }
        s_hi = lo;
    }
    __syncthreads();
    int start = s_lo, end = s_hi;

    int j = threadIdx.x & 63;
    int r = threadIdx.x >> 6;
    const float* h = (const float*)g_h4;

    float acc = 0.f;
    for (int n = start + r; n < end; n += 4)
        acc += h[(size_t)n * HID + j];

    __shared__ float sm[4][64];
    sm[r][j] = acc;
    __syncthreads();

    if (r == 0) {
        float v = sm[0][j] + sm[1][j] + sm[2][j] + sm[3][j];
        float cnt = (float)((end - start) > 0 ? (end - start) : 1);
        float p = v / cnt;
        float w0 = Wfc[j * 2 + 0];
        float w1 = Wfc[j * 2 + 1];
        __syncwarp();
        sm[0][j] = p * w0;
        sm[1][j] = p * w1;
    }
    __syncthreads();

    if (threadIdx.x < 2) {
        float s = 0.f;
        #pragma unroll
        for (int jj = 0; jj < 64; jj++) s += sm[threadIdx.x][jj];
        out[g * 2 + threadIdx.x] = s + bfc[threadIdx.x];
    }
}

// ---------------- launch (fork/join: gemm1 overlaps scan+fill) ----------------
extern "C" void kernel_launch(void* const* d_in, const int* in_sizes, int n_in,
                              void* d_out, int out_size) {
    const float* x     = (const float*)d_in[0];
    const int*   ei    = (const int*)d_in[1];     // int32
    const int*   batch = (const int*)d_in[2];     // int32
    const float* W1    = (const float*)d_in[3];
    const float* b1    = (const float*)d_in[4];
    const float* W2    = (const float*)d_in[5];
    const float* b2    = (const float*)d_in[6];
    const float* Wfc   = (const float*)d_in[7];
    const float* bfc   = (const float*)d_in[8];
    float* out = (float*)d_out;

    // one-time host-side resources (created on uncaptured correctness call)
    static cudaStream_t s2 = nullptr;
    static cudaEvent_t  evA = nullptr, evB = nullptr;
    if (!s2) {
        cudaStreamCreateWithFlags(&s2, cudaStreamNonBlocking);
        cudaEventCreateWithFlags(&evA, cudaEventDisableTiming);
        cudaEventCreateWithFlags(&evB, cudaEventDisableTiming);
    }

    // degrees -> dinv (prerequisite for both branches)
    init_kernel <<<(N_NODES + 255) / 256, 256>>>();
    edge_kernel <<<(N_EDGES / 4 + 255) / 256, 256>>>(ei);
    dinv_kernel <<<(N_NODES + 255) / 256, 256>>>();

    // fork: gemm1 (tensor-core) on s2, CSR build continues on default stream
    cudaEventRecord(evA, 0);
    cudaStreamWaitEvent(s2, evA, 0);
    gemm1_kernel<<<(N_NODES + 63) / 64, 128, 0, s2>>>(x, W1);
    cudaEventRecord(evB, s2);

    scan1_kernel<<<SCAN_NB, SCAN_BS>>>();
    scan2_kernel<<<1, 512>>>();
    scan3_kernel<<<SCAN_NB, SCAN_BS>>>();
    fill_kernel <<<(N_EDGES / 4 + 255) / 256, 256>>>(ei);

    // join
    cudaStreamWaitEvent(0, evB, 0);

    // layer 1 aggregation fused with layer 2 GEMM
    agg1_gemm2_kernel<<<2048, 256>>>(b1, W2);
    // layer 2 aggregation
    agg2_kernel<<<(N_NODES * 16 + 255) / 256, 256>>>(b2);
    // fused mean-pool + FC
    pool_fc_kernel<<<NUM_GRAPHS, 256>>>(batch, Wfc, bfc, out);
}

// round 13
// speedup vs baseline: 1.5347x; 1.0607x over previous
#include <cuda_runtime.h>
#include <cuda_fp16.h>
#include <cstdint>

#define N_NODES    100000
#define N_EDGES    3200000
#define F_IN       128
#define HID        64
#define NUM_GRAPHS 512
#define N_TILES32  ((N_NODES + 31) / 32)                 // 3125

#define SCAN_BS    256
#define SCAN_NB    ((N_NODES + SCAN_BS - 1) / SCAN_BS)   // 391

// ---------------- scratch (static device globals; no allocation) ----------------
__device__ int    g_cnti[N_NODES];
__device__ int    g_fill[N_NODES];
__device__ int    g_offs[N_NODES + 1];
__device__ int    g_part[SCAN_NB];
__device__ int    g_partex[SCAN_NB];
__device__ int    g_csr[N_EDGES];
__device__ uint4  g_hs1h[N_NODES * 8];    // fp16: dinv * (x @ W1); uint4 q = cols 8q..8q+7
__device__ uint4  g_hs2h[N_NODES * 8];    // fp16: dinv * (h1 @ W2)
__device__ uint4  g_h2h [N_NODES * 8];    // fp16 layer-2 output (for pooling)

__device__ __forceinline__ float4 f4add(float4 a, float4 b) {
    return make_float4(a.x + b.x, a.y + b.y, a.z + b.z, a.w + b.w);
}
__device__ __forceinline__ float4 h4lo(uint4 u) {   // halves 0..3
    float2 a = __half22float2(*reinterpret_cast<__half2*>(&u.x));
    float2 b = __half22float2(*reinterpret_cast<__half2*>(&u.y));
    return make_float4(a.x, a.y, b.x, b.y);
}
__device__ __forceinline__ float4 h4hi(uint4 u) {   // halves 4..7
    float2 a = __half22float2(*reinterpret_cast<__half2*>(&u.z));
    float2 b = __half22float2(*reinterpret_cast<__half2*>(&u.w));
    return make_float4(a.x, a.y, b.x, b.y);
}
__device__ __forceinline__ unsigned pack2h(float a, float b) {
    __half2 h = __floats2half2_rn(a, b);
    return *reinterpret_cast<unsigned*>(&h);
}
__device__ __forceinline__ float to_tf32(float x) {
    float r;
    asm("cvt.rna.tf32.f32 %0, %1;" : "=f"(r) : "f"(x));
    return r;
}

// ---------------- init ----------------
__global__ void init_kernel() {
    int i = blockIdx.x * blockDim.x + threadIdx.x;
    if (i < N_NODES) g_cnti[i] = 0;
}

// ---------------- degree count (int4-vectorized) ----------------
__global__ void edge_kernel(const int* __restrict__ ei) {
    int e4 = blockIdx.x * blockDim.x + threadIdx.x;
    if (e4 >= N_EDGES / 4) return;
    int4 c = reinterpret_cast<const int4*>(ei + N_EDGES)[e4];
    atomicAdd(&g_cnti[c.x], 1);
    atomicAdd(&g_cnti[c.y], 1);
    atomicAdd(&g_cnti[c.z], 1);
    atomicAdd(&g_cnti[c.w], 1);
}

// ---------------- 3-kernel exclusive scan of g_cnti -> g_offs ----------------
__global__ void scan1_kernel() {
    __shared__ int s[SCAN_BS];
    int i = blockIdx.x * SCAN_BS + threadIdx.x;
    int v = (i < N_NODES) ? g_cnti[i] : 0;
    s[threadIdx.x] = v;
    __syncthreads();
    #pragma unroll
    for (int d = 1; d < SCAN_BS; d <<= 1) {
        int t = (threadIdx.x >= d) ? s[threadIdx.x - d] : 0;
        __syncthreads();
        s[threadIdx.x] += t;
        __syncthreads();
    }
    if (i < N_NODES) g_offs[i] = s[threadIdx.x] - v;
    if (threadIdx.x == SCAN_BS - 1) g_part[blockIdx.x] = s[SCAN_BS - 1];
}

__global__ void scan2_kernel() {   // one block, 512 threads >= SCAN_NB
    __shared__ int s[512];
    int v = (threadIdx.x < SCAN_NB) ? g_part[threadIdx.x] : 0;
    s[threadIdx.x] = v;
    __syncthreads();
    #pragma unroll
    for (int d = 1; d < 512; d <<= 1) {
        int t = (threadIdx.x >= d) ? s[threadIdx.x - d] : 0;
        __syncthreads();
        s[threadIdx.x] += t;
        __syncthreads();
    }
    if (threadIdx.x < SCAN_NB) g_partex[threadIdx.x] = s[threadIdx.x] - v;
}

__global__ void scan3_kernel() {   // + fill-cursor seed fused
    int i = blockIdx.x * SCAN_BS + threadIdx.x;
    if (i < N_NODES) {
        int o = g_offs[i] + g_partex[blockIdx.x];
        g_offs[i] = o;
        g_fill[i] = o;
    }
    if (i == 0) g_offs[N_NODES] = N_EDGES;
}

// ---------------- CSR fill (int4-vectorized; cursor IS the position) ----------------
__global__ void fill_kernel(const int* __restrict__ ei) {
    int e4 = blockIdx.x * blockDim.x + threadIdx.x;
    if (e4 >= N_EDGES / 4) return;
    int4 r = reinterpret_cast<const int4*>(ei)[e4];
    int4 c = reinterpret_cast<const int4*>(ei + N_EDGES)[e4];
    g_csr[atomicAdd(&g_fill[c.x], 1)] = r.x;
    g_csr[atomicAdd(&g_fill[c.y], 1)] = r.y;
    g_csr[atomicAdd(&g_fill[c.z], 1)] = r.z;
    g_csr[atomicAdd(&g_fill[c.w], 1)] = r.w;
}

// ---------------- GEMM1 via tf32 tensor cores: hs1 = fp16( dinv * (X @ W1) ) ----------------
__global__ __launch_bounds__(128) void gemm1_kernel(const float* __restrict__ X,
                                                    const float* __restrict__ W) {
    __shared__ float Wsm[F_IN * 72];    // [k][n], n padded 64->72

    int tid = threadIdx.x;
    for (int i2 = tid; i2 < F_IN * HID / 2; i2 += 128) {
        float2 w = reinterpret_cast<const float2*>(W)[i2];
        int k = i2 >> 5, n2 = i2 & 31;
        Wsm[k * 72 + n2 * 2]     = to_tf32(w.x);
        Wsm[k * 72 + n2 * 2 + 1] = to_tf32(w.y);
    }

    int wid  = tid >> 5, lane = tid & 31;
    int gid  = lane >> 2;          // 0..7
    int tig  = lane & 3;           // 0..3
    int node0 = (blockIdx.x * 4 + wid) * 16;
    int r0 = node0 + gid;
    int r1 = node0 + gid + 8;
    bool v0 = r0 < N_NODES, v1 = r1 < N_NODES;

    float a[16][4];
    #pragma unroll
    for (int c = 0; c < 16; c++) {
        int k0 = c * 8 + tig;
        a[c][0] = v0 ? X[(size_t)r0 * F_IN + k0]     : 0.f;
        a[c][1] = v1 ? X[(size_t)r1 * F_IN + k0]     : 0.f;
        a[c][2] = v0 ? X[(size_t)r0 * F_IN + k0 + 4] : 0.f;
        a[c][3] = v1 ? X[(size_t)r1 * F_IN + k0 + 4] : 0.f;
    }
    #pragma unroll
    for (int c = 0; c < 16; c++) {
        a[c][0] = to_tf32(a[c][0]); a[c][1] = to_tf32(a[c][1]);
        a[c][2] = to_tf32(a[c][2]); a[c][3] = to_tf32(a[c][3]);
    }

    float di0 = v0 ? rsqrtf(1.0f + (float)g_cnti[r0]) : 0.f;
    float di1 = v1 ? rsqrtf(1.0f + (float)g_cnti[r1]) : 0.f;
    __syncthreads();

    unsigned* outp = reinterpret_cast<unsigned*>(g_hs1h);   // uint j = cols 2j,2j+1

    #pragma unroll
    for (int nb = 0; nb < 8; nb++) {
        float c0 = 0.f, c1 = 0.f, c2 = 0.f, c3 = 0.f;
        #pragma unroll
        for (int kc = 0; kc < 16; kc++) {
            float b0 = Wsm[(kc * 8 + tig)     * 72 + nb * 8 + gid];
            float b1 = Wsm[(kc * 8 + tig + 4) * 72 + nb * 8 + gid];
            asm volatile(
                "mma.sync.aligned.m16n8k8.row.col.f32.tf32.tf32.f32 "
                "{%0,%1,%2,%3}, {%4,%5,%6,%7}, {%8,%9}, {%0,%1,%2,%3};"
                : "+f"(c0), "+f"(c1), "+f"(c2), "+f"(c3)
                : "r"(__float_as_uint(a[kc][0])), "r"(__float_as_uint(a[kc][1])),
                  "r"(__float_as_uint(a[kc][2])), "r"(__float_as_uint(a[kc][3])),
                  "r"(__float_as_uint(b0)), "r"(__float_as_uint(b1)));
        }
        if (v0) outp[(size_t)r0 * 32 + nb * 4 + tig] = pack2h(c0 * di0, c1 * di0);
        if (v1) outp[(size_t)r1 * 32 + nb * 4 + tig] = pack2h(c2 * di1, c3 * di1);
    }
}

// ---------------- fused: agg layer1 (8 lanes/node uint4 gather) -> in-block GEMM @W2 ----------------
// 256 threads = 32 nodes x 8 lanes. Lane cg owns cols 8cg..8cg+7 (phase A)
// and cols {4cg..4cg+3, 32+4cg..32+4cg+3} (phase B). Direct (broadcast) csr loads.
__global__ __launch_bounds__(256) void agg1_gemm2_kernel(const float* __restrict__ b1,
                                                         const float* __restrict__ W2) {
    __shared__ float4 W2s[HID * 16];   // W2s[k*16 + h*8 + cg] = W2[k][h*32+cg*4 .. +3]
    __shared__ float  hsm[32 * 68];    // 32 nodes x 64 cols (pad 68)

    int tid = threadIdx.x;
    for (int i = tid; i < HID * 16; i += 256) {
        int k = i >> 4, q = i & 15;
        int h = q >> 3, cg = q & 7;
        W2s[i] = *reinterpret_cast<const float4*>(&W2[k * HID + h * 32 + cg * 4]);
    }

    int sub = tid >> 3;            // node within tile, 0..31
    int cg  = tid & 7;             // lane in group
    float4 bb0 = reinterpret_cast<const float4*>(b1)[cg * 2];
    float4 bb1 = reinterpret_cast<const float4*>(b1)[cg * 2 + 1];

    for (int tile = blockIdx.x; tile < N_TILES32; tile += gridDim.x) {
        int node = tile * 32 + sub;
        int s = g_offs[node];
        int e = g_offs[node + 1];

        uint4 su = g_hs1h[(size_t)node * 8 + cg];      // self loop
        float4 aLo = h4lo(su), aHi = h4hi(su);

        int j = s;
        for (; j + 7 < e; j += 8) {
            int i0 = g_csr[j],     i1 = g_csr[j + 1], i2 = g_csr[j + 2], i3 = g_csr[j + 3];
            int i4 = g_csr[j + 4], i5 = g_csr[j + 5], i6 = g_csr[j + 6], i7 = g_csr[j + 7];
            uint4 v0 = g_hs1h[(size_t)i0 * 8 + cg];
            uint4 v1 = g_hs1h[(size_t)i1 * 8 + cg];
            uint4 v2 = g_hs1h[(size_t)i2 * 8 + cg];
            uint4 v3 = g_hs1h[(size_t)i3 * 8 + cg];
            uint4 v4 = g_hs1h[(size_t)i4 * 8 + cg];
            uint4 v5 = g_hs1h[(size_t)i5 * 8 + cg];
            uint4 v6 = g_hs1h[(size_t)i6 * 8 + cg];
            uint4 v7 = g_hs1h[(size_t)i7 * 8 + cg];
            aLo = f4add(aLo, f4add(f4add(f4add(h4lo(v0), h4lo(v1)), f4add(h4lo(v2), h4lo(v3))),
                                   f4add(f4add(h4lo(v4), h4lo(v5)), f4add(h4lo(v6), h4lo(v7)))));
            aHi = f4add(aHi, f4add(f4add(f4add(h4hi(v0), h4hi(v1)), f4add(h4hi(v2), h4hi(v3))),
                                   f4add(f4add(h4hi(v4), h4hi(v5)), f4add(h4hi(v6), h4hi(v7)))));
        }
        for (; j < e; j++) {
            uint4 v = g_hs1h[(size_t)g_csr[j] * 8 + cg];
            aLo = f4add(aLo, h4lo(v));
            aHi = f4add(aHi, h4hi(v));
        }

        float di = rsqrtf(1.0f + (float)g_cnti[node]);
        float r0 = fmaxf(di * aLo.x + bb0.x, 0.f);
        float r1 = fmaxf(di * aLo.y + bb0.y, 0.f);
        float r2 = fmaxf(di * aLo.z + bb0.z, 0.f);
        float r3 = fmaxf(di * aLo.w + bb0.w, 0.f);
        float r4 = fmaxf(di * aHi.x + bb1.x, 0.f);
        float r5 = fmaxf(di * aHi.y + bb1.y, 0.f);
        float r6 = fmaxf(di * aHi.z + bb1.z, 0.f);
        float r7 = fmaxf(di * aHi.w + bb1.w, 0.f);

        __syncthreads();                 // prior tile's phase-B reads done
        float* hp = &hsm[sub * 68 + cg * 8];
        hp[0] = r0; hp[1] = r1; hp[2] = r2; hp[3] = r3;
        hp[4] = r4; hp[5] = r5; hp[6] = r6; hp[7] = r7;
        __syncthreads();

        // phase B: hs2 = fp16( dinv * (h1 @ W2) )
        float c0 = 0.f, c1 = 0.f, c2 = 0.f, c3 = 0.f;
        float c4 = 0.f, c5 = 0.f, c6 = 0.f, c7 = 0.f;
        const float* hrow = &hsm[sub * 68];
        #pragma unroll 8
        for (int k = 0; k < HID; k++) {
            float xv = hrow[k];
            float4 w0 = W2s[k * 16 + cg];        // cols 4cg..4cg+3
            float4 w1 = W2s[k * 16 + 8 + cg];    // cols 32+4cg..+3
            c0 += xv * w0.x; c1 += xv * w0.y; c2 += xv * w0.z; c3 += xv * w0.w;
            c4 += xv * w1.x; c5 += xv * w1.y; c6 += xv * w1.z; c7 += xv * w1.w;
        }
        uint2* o = reinterpret_cast<uint2*>(g_hs2h);   // uint2 q = cols 4q..4q+3
        uint2 ulo, uhi;
        ulo.x = pack2h(c0 * di, c1 * di); ulo.y = pack2h(c2 * di, c3 * di);
        uhi.x = pack2h(c4 * di, c5 * di); uhi.y = pack2h(c6 * di, c7 * di);
        o[(size_t)node * 16 + cg]     = ulo;
        o[(size_t)node * 16 + 8 + cg] = uhi;
    }
}

// ---------------- agg layer2: h2 = fp16( relu(dinv*(hs2_self + sum hs2_src) + b2) ) ----------------
__global__ __launch_bounds__(256) void agg2_kernel(const float* __restrict__ b) {
    int t = blockIdx.x * 256 + threadIdx.x;
    int node = t >> 3;
    if (node >= N_NODES) return;
    int cg = t & 7;

    int s = g_offs[node];
    int e = g_offs[node + 1];

    uint4 su = g_hs2h[(size_t)node * 8 + cg];
    float4 aLo = h4lo(su), aHi = h4hi(su);

    int j = s;
    for (; j + 7 < e; j += 8) {
        int i0 = g_csr[j],     i1 = g_csr[j + 1], i2 = g_csr[j + 2], i3 = g_csr[j + 3];
        int i4 = g_csr[j + 4], i5 = g_csr[j + 5], i6 = g_csr[j + 6], i7 = g_csr[j + 7];
        uint4 v0 = g_hs2h[(size_t)i0 * 8 + cg];
        uint4 v1 = g_hs2h[(size_t)i1 * 8 + cg];
        uint4 v2 = g_hs2h[(size_t)i2 * 8 + cg];
        uint4 v3 = g_hs2h[(size_t)i3 * 8 + cg];
        uint4 v4 = g_hs2h[(size_t)i4 * 8 + cg];
        uint4 v5 = g_hs2h[(size_t)i5 * 8 + cg];
        uint4 v6 = g_hs2h[(size_t)i6 * 8 + cg];
        uint4 v7 = g_hs2h[(size_t)i7 * 8 + cg];
        aLo = f4add(aLo, f4add(f4add(f4add(h4lo(v0), h4lo(v1)), f4add(h4lo(v2), h4lo(v3))),
                               f4add(f4add(h4lo(v4), h4lo(v5)), f4add(h4lo(v6), h4lo(v7)))));
        aHi = f4add(aHi, f4add(f4add(f4add(h4hi(v0), h4hi(v1)), f4add(h4hi(v2), h4hi(v3))),
                               f4add(f4add(h4hi(v4), h4hi(v5)), f4add(h4hi(v6), h4hi(v7)))));
    }
    for (; j < e; j++) {
        uint4 v = g_hs2h[(size_t)g_csr[j] * 8 + cg];
        aLo = f4add(aLo, h4lo(v));
        aHi = f4add(aHi, h4hi(v));
    }

    float di = rsqrtf(1.0f + (float)g_cnti[node]);
    float4 bb0 = reinterpret_cast<const float4*>(b)[cg * 2];
    float4 bb1 = reinterpret_cast<const float4*>(b)[cg * 2 + 1];
    uint4 o;
    o.x = pack2h(fmaxf(di * aLo.x + bb0.x, 0.f), fmaxf(di * aLo.y + bb0.y, 0.f));
    o.y = pack2h(fmaxf(di * aLo.z + bb0.z, 0.f), fmaxf(di * aLo.w + bb0.w, 0.f));
    o.z = pack2h(fmaxf(di * aHi.x + bb1.x, 0.f), fmaxf(di * aHi.y + bb1.y, 0.f));
    o.w = pack2h(fmaxf(di * aHi.z + bb1.z, 0.f), fmaxf(di * aHi.w + bb1.w, 0.f));
    g_h2h[(size_t)node * 8 + cg] = o;
}

// ---------------- fused mean-pool + FC (batch sorted int32; h2 is fp16) ----------------
__global__ __launch_bounds__(256) void pool_fc_kernel(const int* __restrict__ batch,
                                                      const float* __restrict__ Wfc,
                                                      const float* __restrict__ bfc,
                                                      float* __restrict__ out) {
    int g = blockIdx.x;
    __shared__ int s_lo, s_hi;
    if (threadIdx.x == 0) {
        int lo = 0, hi = N_NODES;
        while (lo < hi) { int m = (lo + hi) >> 1; if (batch[m] < g) lo = m + 1; else hi = m; }
        s_lo = lo;
        lo = 0; hi = N_NODES;
        while (lo < hi) { int m = (lo + hi) >> 1; if (batch[m] < g + 1) lo = m + 1; else hi = m; }
        s_hi = lo;
    }
    __syncthreads();
    int start = s_lo, end = s_hi;

    int lane = threadIdx.x & 31;   // col pair (cols 2lane, 2lane+1)
    int r    = threadIdx.x >> 5;   // 0..7
    const unsigned* h = reinterpret_cast<const unsigned*>(g_h2h);   // 32 uints/node

    float ax = 0.f, ay = 0.f;
    for (int n = start + r; n < end; n += 8) {
        unsigned u = h[(size_t)n * 32 + lane];
        float2 f = __half22float2(*reinterpret_cast<__half2*>(&u));
        ax += f.x; ay += f.y;
    }

    __shared__ float2 sm[8][32];
    sm[r][lane] = make_float2(ax, ay);
    __syncthreads();

    if (threadIdx.x < 32) {
        float px = 0.f, py = 0.f;
        #pragma unroll
        for (int k = 0; k < 8; k++) { px += sm[k][lane].x; py += sm[k][lane].y; }
        float cnt = (float)((end - start) > 0 ? (end - start) : 1);
        px /= cnt; py /= cnt;
        int j0 = lane * 2, j1 = lane * 2 + 1;
        float v0 = px * Wfc[j0 * 2]     + py * Wfc[j1 * 2];
        float v1 = px * Wfc[j0 * 2 + 1] + py * Wfc[j1 * 2 + 1];
        #pragma unroll
        for (int off = 16; off; off >>= 1) {
            v0 += __shfl_down_sync(0xffffffffu, v0, off);
            v1 += __shfl_down_sync(0xffffffffu, v1, off);
        }
        if (lane == 0) {
            out[g * 2 + 0] = v0 + bfc[0];
            out[g * 2 + 1] = v1 + bfc[1];
        }
    }
}

// ---------------- launch (fork/join: gemm1 overlaps scan+fill) ----------------
extern "C" void kernel_launch(void* const* d_in, const int* in_sizes, int n_in,
                              void* d_out, int out_size) {
    const float* x     = (const float*)d_in[0];
    const int*   ei    = (const int*)d_in[1];     // int32
    const int*   batch = (const int*)d_in[2];     // int32
    const float* W1    = (const float*)d_in[3];
    const float* b1    = (const float*)d_in[4];
    const float* W2    = (const float*)d_in[5];
    const float* b2    = (const float*)d_in[6];
    const float* Wfc   = (const float*)d_in[7];
    const float* bfc   = (const float*)d_in[8];
    float* out = (float*)d_out;

    static cudaStream_t s2 = nullptr;
    static cudaEvent_t  evA = nullptr, evB = nullptr;
    if (!s2) {
        cudaStreamCreateWithFlags(&s2, cudaStreamNonBlocking);
        cudaEventCreateWithFlags(&evA, cudaEventDisableTiming);
        cudaEventCreateWithFlags(&evB, cudaEventDisableTiming);
    }

    // degrees (prerequisite for both branches)
    init_kernel <<<(N_NODES + 255) / 256, 256>>>();
    edge_kernel <<<(N_EDGES / 4 + 255) / 256, 256>>>(ei);

    // fork: gemm1 (tensor-core, computes dinv inline) on s2
    cudaEventRecord(evA, 0);
    cudaStreamWaitEvent(s2, evA, 0);
    gemm1_kernel<<<(N_NODES + 63) / 64, 128, 0, s2>>>(x, W1);
    cudaEventRecord(evB, s2);

    scan1_kernel<<<SCAN_NB, SCAN_BS>>>();
    scan2_kernel<<<1, 512>>>();
    scan3_kernel<<<SCAN_NB, SCAN_BS>>>();
    fill_kernel <<<(N_EDGES / 4 + 255) / 256, 256>>>(ei);

    // join
    cudaStreamWaitEvent(0, evB, 0);

    agg1_gemm2_kernel<<<N_TILES32, 256>>>(b1, W2);
    agg2_kernel<<<(N_NODES * 8 + 255) / 256, 256>>>(b2);
    pool_fc_kernel<<<NUM_GRAPHS, 256>>>(batch, Wfc, bfc, out);
}